// round 14
// baseline (speedup 1.0000x reference)
#include <cuda_runtime.h>
#include <cuda_fp16.h>
#include <cstdint>

// Problem constants (fixed shapes)
#define BQ  16
#define CC  256
#define HH  48
#define WW  48
#define NN  (HH*WW)      // 2304
#define KNN 8
#define KB  12           // per-tile candidate list length (sorted, best-first)
#define NSLOT 18         // one list per tile stripe
#define NLIST (NSLOT*KB) // 216 packed candidates per node
#define NCAND 12         // merged candidates that get exact rescore
#define TILE 128
#define NTILES (NN/TILE) // 18
#define NPAIR  171       // NTILES*(NTILES+1)/2

// gram smem layout (bytes); fp16 chunk row = 64 fp16 (128B) + 16 pad = 144
#define CRW    144
#define SMB_A0 0                   // also reused as merge buffer after MMA
#define SMB_A1 18432
#define SMB_B0 36864
#define SMB_B1 55296
#define SMB_SC 73728               // half2[128][65] = 33280
#define SCH2   65
#define SMB_SQI 107008             // half[128] (256 B)
#define SMB_SQJ 107264             // half[128] (256 B)
#define SMB_TOT 107520

#define PK_INIT 0xFC00FFFFu        // packed +inf key | idx 0xFFFF

// Scratch (device globals; no allocation allowed)
__device__ __align__(256) float    g_nodesT[BQ * NN * CC];  // fp32 features [B][N][C]
__device__ __align__(256) __half   g_half[BQ * NN * CC];    // fp16 copy for filter GEMM
__device__ __align__(256) float    g_sq[BQ * NN];           // squared norms
__device__ __align__(256) uint32_t g_ps[(size_t)BQ * NN * NLIST]; // packed cand lists

__device__ __forceinline__ uint32_t smem_u32(const void* p) {
    uint32_t a;
    asm("{ .reg .u64 t; cvta.to.shared.u64 t, %1; cvt.u32.u64 %0, t; }"
        : "=r"(a) : "l"(p));
    return a;
}
#define CP_ASYNC16(dst, src) \
    asm volatile("cp.async.cg.shared.global [%0], [%1], 16;" :: "r"(dst), "l"(src))
#define CP_COMMIT() asm volatile("cp.async.commit_group;" ::: "memory")
#define CP_WAIT(n)  asm volatile("cp.async.wait_group %0;" :: "n"(n) : "memory")

#define LDSM_X4(r0, r1, r2, r3, addr) \
    asm volatile("ldmatrix.sync.aligned.m8n8.x4.shared.b16 {%0,%1,%2,%3}, [%4];" \
        : "=r"(r0), "=r"(r1), "=r"(r2), "=r"(r3) : "r"(addr))

#define HMMA16(acc0, acc1, a0, a1, a2, a3, b0, b1) \
    asm volatile("mma.sync.aligned.m16n8k16.row.col.f16.f16.f16.f16 " \
        "{%0,%1}, {%2,%3,%4,%5}, {%6,%7}, {%0,%1};" \
        : "+r"(acc0), "+r"(acc1) \
        : "r"(a0), "r"(a1), "r"(a2), "r"(a3), "r"(b0), "r"(b1))

// half -> monotone u16 (asc uint == asc value)
__device__ __forceinline__ uint32_t h2mono(__half x) {
    unsigned short h = __half_as_ushort(x);
    unsigned short m = (unsigned short)(h ^ ((h & 0x8000) ? 0xFFFFu : 0x8000u));
    return (uint32_t)m;
}
// monotone u16 (hi half of packed) -> half
__device__ __forceinline__ __half mono2h(uint32_t p) {
    unsigned short m = (unsigned short)(p >> 16);
    unsigned short h = (unsigned short)(m ^ ((m & 0x8000) ? 0x8000u : 0xFFFFu));
    return __ushort_as_half(h);
}

// packed insert into uint32 top-KB list ([0] = worst/largest)
#define PINS(lst, p) do { \
    if ((p) < (lst)[0]) { \
        (lst)[0] = (p); \
        _Pragma("unroll") \
        for (int _t = 0; _t < KB - 1; ++_t) { \
            uint32_t _lo = min((lst)[_t], (lst)[_t + 1]); \
            uint32_t _hi = max((lst)[_t], (lst)[_t + 1]); \
            (lst)[_t] = _hi; (lst)[_t + 1] = _lo; \
        } \
    } \
} while (0)

// ---------------------------------------------------------------------------
// Kernel 1: transpose F[b][c][n] -> nodesT[b][n][c] (fp32 + fp16 copies)
// ---------------------------------------------------------------------------
__global__ void k_transpose(const float* __restrict__ F) {
    __shared__ float t[32][33];
    int b  = blockIdx.z;
    int n0 = blockIdx.x * 32;
    int c0 = blockIdx.y * 32;
    const float* Fb = F + (size_t)b * CC * NN;
    int tx = threadIdx.x, ty = threadIdx.y;  // 32 x 8
#pragma unroll
    for (int i = 0; i < 32; i += 8)
        t[ty + i][tx] = Fb[(size_t)(c0 + ty + i) * NN + n0 + tx];
    __syncthreads();
    float* out = g_nodesT + (size_t)b * NN * CC;
    __half* outh = g_half + (size_t)b * NN * CC;
#pragma unroll
    for (int i = 0; i < 32; i += 8) {
        float v = t[tx][ty + i];
        size_t o = (size_t)(n0 + ty + i) * CC + c0 + tx;
        out[o]  = v;
        outh[o] = __float2half(v);
    }
}

// ---------------------------------------------------------------------------
// Kernel 2: squared norms from g_nodesT (coalesced; warp per node)
// ---------------------------------------------------------------------------
__global__ void k_sq() {
    const int wid  = threadIdx.x >> 5;
    const int lane = threadIdx.x & 31;
    const int n = blockIdx.x * 8 + wid;
    const int b = blockIdx.y;
    const float* p = g_nodesT + (size_t)(b * NN + n) * CC + lane * 8;
    float4 a = *(const float4*)p;
    float4 c = *(const float4*)(p + 4);
    float s = a.x*a.x + a.y*a.y + a.z*a.z + a.w*a.w
            + c.x*c.x + c.y*c.y + c.z*c.z + c.w*c.w;
#pragma unroll
    for (int o = 16; o > 0; o >>= 1) s += __shfl_xor_sync(0xffffffffu, s, o);
    if (lane == 0) g_sq[b * NN + n] = s;
}

// ---------------------------------------------------------------------------
// Kernel 3: symmetric fp16 Gram — one CTA per tile-pair (it <= jt).
// (Byte-identical to R13 — near the legacy-HMMA pipe floor.)
// ---------------------------------------------------------------------------
__global__ __launch_bounds__(256, 2) void k_gram_sym() {
    extern __shared__ unsigned char smraw[];
    const uint32_t smb = smem_u32(smraw);
    uint32_t* Scw  = (uint32_t*)(smraw + SMB_SC);  // half2[128][65]
    __half*   sqih = (__half*)(smraw + SMB_SQI);   // [128]
    __half*   sqjh = (__half*)(smraw + SMB_SQJ);   // [128]
    uint32_t (*mbuf)[KB] = (uint32_t (*)[KB])(smraw + SMB_A0);  // overlay

    const int b = blockIdx.y;
    int tlin = blockIdx.x, it = 0;
    while (tlin >= NTILES - it) { tlin -= NTILES - it; ++it; }
    const int jt = it + tlin;
    const int i0 = it * TILE, j0 = jt * TILE;

    const int tid = threadIdx.x;
    const int wid  = tid >> 5;
    const int lane = tid & 31;
    const int wm = wid >> 1;
    const int wn = wid & 1;
    const int grp = lane >> 2;
    const int tig = lane & 3;
    const int quad = lane >> 3;
    const int wi   = lane & 7;
    const __half* Hb = g_half + (size_t)b * NN * CC;

    const int crow  = tid >> 1;
    const int chalf = tid & 1;

    uint32_t aoff[2], boff[4];
#pragma unroll
    for (int mt = 0; mt < 2; ++mt) {
        int row = wm * 32 + mt * 16 + wi + 8 * (quad & 1);
        aoff[mt] = row * CRW + (quad >> 1) * 16;
    }
#pragma unroll
    for (int p = 0; p < 4; ++p) {
        int row = wn * 64 + p * 16 + wi + 8 * (quad >> 1);
        boff[p] = row * CRW + (quad & 1) * 16;
    }

    auto issue = [&](int q) {
        const int c = q, buf = q & 1;
        const char* asrc =
            (const char*)(Hb + (size_t)(i0 + crow) * CC + c * 64 + chalf * 32);
        const char* bsrc =
            (const char*)(Hb + (size_t)(j0 + crow) * CC + c * 64 + chalf * 32);
        uint32_t adst = smb + (buf ? SMB_A1 : SMB_A0) + crow * CRW + chalf * 64;
        uint32_t bdst = smb + (buf ? SMB_B1 : SMB_B0) + crow * CRW + chalf * 64;
#pragma unroll
        for (int i = 0; i < 4; ++i) {
            CP_ASYNC16(adst + i * 16, asrc + i * 16);
            CP_ASYNC16(bdst + i * 16, bsrc + i * 16);
        }
        CP_COMMIT();
    };

    issue(0);

    uint32_t acc[2][8][2];
#pragma unroll
    for (int mt = 0; mt < 2; ++mt)
#pragma unroll
        for (int nt = 0; nt < 8; ++nt)
            acc[mt][nt][0] = acc[mt][nt][1] = 0u;

    for (int q = 0; q < 4; ++q) {
        if (q + 1 < 4) { issue(q + 1); CP_WAIT(1); }
        else           {               CP_WAIT(0); }
        __syncthreads();

        if (q == 0 && tid < TILE) {
            sqih[tid] = __float2half(g_sq[b * NN + i0 + tid]);
            sqjh[tid] = __float2half(g_sq[b * NN + j0 + tid]);
        }

        const uint32_t abase = smb + ((q & 1) ? SMB_A1 : SMB_A0);
        const uint32_t bbase = smb + ((q & 1) ? SMB_B1 : SMB_B0);
#pragma unroll
        for (int ks = 0; ks < 4; ++ks) {
            const int ko = ks * 32;
            uint32_t a[2][4];
#pragma unroll
            for (int mt = 0; mt < 2; ++mt)
                LDSM_X4(a[mt][0], a[mt][1], a[mt][2], a[mt][3],
                        abase + aoff[mt] + ko);
            uint32_t bb[4][4];
#pragma unroll
            for (int p = 0; p < 4; ++p)
                LDSM_X4(bb[p][0], bb[p][1], bb[p][2], bb[p][3],
                        bbase + boff[p] + ko);
#pragma unroll
            for (int mt = 0; mt < 2; ++mt)
#pragma unroll
                for (int p = 0; p < 4; ++p) {
                    HMMA16(acc[mt][2*p][0],   acc[mt][2*p][1],
                           a[mt][0], a[mt][1], a[mt][2], a[mt][3],
                           bb[p][0], bb[p][1]);
                    HMMA16(acc[mt][2*p+1][0], acc[mt][2*p+1][1],
                           a[mt][0], a[mt][1], a[mt][2], a[mt][3],
                           bb[p][2], bb[p][3]);
                }
        }
        __syncthreads();
    }

#pragma unroll
    for (int mt = 0; mt < 2; ++mt) {
        const int r0 = wm * 32 + mt * 16 + grp;
        const int cp = wn * 32 + tig;
#pragma unroll
        for (int nt = 0; nt < 8; ++nt) {
            Scw[r0 * SCH2 + cp + nt * 4]       = acc[mt][nt][0];
            Scw[(r0 + 8) * SCH2 + cp + nt * 4] = acc[mt][nt][1];
        }
    }
    __syncthreads();

    const bool diag = (it == jt);
    if (diag) {
        if (tid < TILE)
            ((__half*)Scw)[tid * (SCH2 * 2) + tid] = __ushort_as_half(0xFC00);
        __syncthreads();
    }

    uint32_t lst[KB];

    // ---- row-side scan ----
    {
        const int srow  = tid >> 1;
        const int shalf = tid & 1;
        const int ig    = i0 + srow;
#pragma unroll
        for (int k = 0; k < KB; ++k) lst[k] = PK_INIT;
        const __half2* srcrow = (const __half2*)Scw + srow * SCH2 + shalf * 32;
        const __half2* sq2    = (const __half2*)sqjh + shalf * 32;
        const int jbase = j0 + shalf * 64;
        const __half2 mtwo2 = __float2half2_rn(-2.0f);
        __half2 th2 = __half2half2(mono2h(lst[0]));
#pragma unroll 4
        for (int s = 0; s < 32; ++s) {
            __half2 key2 = __hfma2(srcrow[s], mtwo2, sq2[s]);
            if (!__hbge2(key2, th2)) {
                const int je = jbase + 2 * s;
                uint32_t p0 = (h2mono(__low2half(key2))  << 16) | (uint32_t)je;
                uint32_t p1 = (h2mono(__high2half(key2)) << 16) | (uint32_t)(je + 1);
                PINS(lst, p0);
                PINS(lst, p1);
                th2 = __half2half2(mono2h(lst[0]));
            }
        }
#pragma unroll
        for (int k = 0; k < KB; ++k) mbuf[tid][k] = lst[k];
        __syncwarp();
        if (shalf == 0) {
            int ia = KB - 1, ib = KB - 1;
            size_t base = ((size_t)(b * NN + ig) * NSLOT + jt) * KB;
#pragma unroll
            for (int t = 0; t < KB; ++t) {
                uint32_t va = mbuf[tid][ia], vb = mbuf[tid + 1][ib];
                if (va < vb) { g_ps[base + t] = va; --ia; }
                else         { g_ps[base + t] = vb; --ib; }
            }
        }
        __syncwarp();
    }

    // ---- col-side scan ----
    if (!diag) {
        const int c  = tid >> 1;
        const int hh = tid & 1;
#pragma unroll
        for (int k = 0; k < KB; ++k) lst[k] = PK_INIT;
        const __half* Sch = (const __half*)Scw;
        const __half mtwo = __float2half(-2.0f);
        __half th = mono2h(lst[0]);
#pragma unroll 4
        for (int r = 0; r < 64; ++r) {
            const int row = hh * 64 + r;
            __half d = Sch[row * (SCH2 * 2) + c];
            __half key = __hfma(d, mtwo, sqih[row]);
            if (__hlt(key, th)) {
                uint32_t p = (h2mono(key) << 16) | (uint32_t)(i0 + row);
                PINS(lst, p);
                th = mono2h(lst[0]);
            }
        }
#pragma unroll
        for (int k = 0; k < KB; ++k) mbuf[tid][k] = lst[k];
        __syncwarp();
        if (hh == 0) {
            int ia = KB - 1, ib = KB - 1;
            size_t base = ((size_t)(b * NN + j0 + c) * NSLOT + it) * KB;
#pragma unroll
            for (int t = 0; t < KB; ++t) {
                uint32_t va = mbuf[tid][ia], vb = mbuf[tid + 1][ib];
                if (va < vb) { g_ps[base + t] = va; --ia; }
                else         { g_ps[base + t] = vb; --ib; }
            }
        }
    }
}

// ---------------------------------------------------------------------------
// Kernel 4: tournament-merge 18 sorted lists -> top-12 by filter score,
// exact fp32 rescore (accumulating the 12-row sum) -> top-8, aggregate by
// subtracting the 4 loser rows; residual + LayerNorm.
// ---------------------------------------------------------------------------
__global__ __launch_bounds__(256) void k_refine(const float* __restrict__ gamma,
                                                const float* __restrict__ beta,
                                                float* __restrict__ out) {
    const int b    = blockIdx.y;
    const int wid  = threadIdx.x >> 5;
    const int lane = threadIdx.x & 31;
    const int n0   = blockIdx.x * 8;
    const int n    = n0 + wid;
    const int h = n / WW, w = n % WW;
    const float* Nb = g_nodesT + (size_t)b * NN * CC;

    const float* xi = Nb + (size_t)n * CC + lane * 8;
    float4 x0 = *(const float4*)xi;
    float4 x1 = *(const float4*)(xi + 4);

    // ---- load this node's 216 packed candidates (coalesced via smem) ----
    __shared__ uint32_t stage[8][224];
    {
        size_t base = (size_t)(b * NN + n) * NLIST;
#pragma unroll
        for (int k = 0; k < 7; ++k) {
            int e = lane + k * 32;
            stage[wid][e] = (e < NLIST) ? g_ps[base + e] : 0xFFFFFFFFu;
        }
    }
    __syncwarp();

    // ---- tournament: lane l < NSLOT owns sorted list l (best-first) ----
    uint32_t head = 0xFFFFFFFFu;
    int hp = 0;
    if (lane < NSLOT) head = stage[wid][lane * KB];
    uint32_t cword = 0xFFFFFFFFu;
#pragma unroll
    for (int t = 0; t < NCAND; ++t) {
        uint32_t wmv = __reduce_min_sync(0xffffffffu, head);
        if (lane == t) cword = wmv;
        unsigned msk = __ballot_sync(0xffffffffu, head == wmv);
        if (lane == (__ffs(msk) - 1)) {
            ++hp;
            head = (hp < KB) ? stage[wid][lane * KB + hp] : 0xFFFFFFFFu;
        }
    }
    int cand = (int)(cword & 0xFFFFu);

    // ---- exact rescore of NCAND candidates, 4 at a time; accumulate sum ----
    float acc[8];
#pragma unroll
    for (int r2 = 0; r2 < 8; ++r2) acc[r2] = 0.f;

    float mykey = 3.0e38f;
    int   myidx = cand;
#pragma unroll
    for (int k0 = 0; k0 < NCAND; k0 += 4) {
        int j0i = __shfl_sync(0xffffffffu, cand, k0);
        int j1i = __shfl_sync(0xffffffffu, cand, k0 + 1);
        int j2i = __shfl_sync(0xffffffffu, cand, k0 + 2);
        int j3i = __shfl_sync(0xffffffffu, cand, k0 + 3);
        const float* r0p = Nb + (size_t)j0i * CC + lane * 8;
        const float* r1p = Nb + (size_t)j1i * CC + lane * 8;
        const float* r2p = Nb + (size_t)j2i * CC + lane * 8;
        const float* r3p = Nb + (size_t)j3i * CC + lane * 8;
        float4 a0 = *(const float4*)r0p, a1 = *(const float4*)(r0p + 4);
        float4 b0 = *(const float4*)r1p, b1 = *(const float4*)(r1p + 4);
        float4 c0 = *(const float4*)r2p, c1 = *(const float4*)(r2p + 4);
        float4 d0 = *(const float4*)r3p, d1 = *(const float4*)(r3p + 4);
        // accumulate candidate-row sum (channel-wise) while data is live
        acc[0] += a0.x + b0.x + c0.x + d0.x;
        acc[1] += a0.y + b0.y + c0.y + d0.y;
        acc[2] += a0.z + b0.z + c0.z + d0.z;
        acc[3] += a0.w + b0.w + c0.w + d0.w;
        acc[4] += a1.x + b1.x + c1.x + d1.x;
        acc[5] += a1.y + b1.y + c1.y + d1.y;
        acc[6] += a1.z + b1.z + c1.z + d1.z;
        acc[7] += a1.w + b1.w + c1.w + d1.w;
        float p0 = x0.x*a0.x + x0.y*a0.y + x0.z*a0.z + x0.w*a0.w
                 + x1.x*a1.x + x1.y*a1.y + x1.z*a1.z + x1.w*a1.w;
        float p1 = x0.x*b0.x + x0.y*b0.y + x0.z*b0.z + x0.w*b0.w
                 + x1.x*b1.x + x1.y*b1.y + x1.z*b1.z + x1.w*b1.w;
        float p2 = x0.x*c0.x + x0.y*c0.y + x0.z*c0.z + x0.w*c0.w
                 + x1.x*c1.x + x1.y*c1.y + x1.z*c1.z + x1.w*c1.w;
        float p3 = x0.x*d0.x + x0.y*d0.y + x0.z*d0.z + x0.w*d0.w
                 + x1.x*d1.x + x1.y*d1.y + x1.z*d1.z + x1.w*d1.w;
#pragma unroll
        for (int o = 16; o > 0; o >>= 1) {
            p0 += __shfl_xor_sync(0xffffffffu, p0, o);
            p1 += __shfl_xor_sync(0xffffffffu, p1, o);
            p2 += __shfl_xor_sync(0xffffffffu, p2, o);
            p3 += __shfl_xor_sync(0xffffffffu, p3, o);
        }
        if (lane == k0)     mykey = g_sq[b * NN + j0i] - 2.0f * p0;
        if (lane == k0 + 1) mykey = g_sq[b * NN + j1i] - 2.0f * p1;
        if (lane == k0 + 2) mykey = g_sq[b * NN + j2i] - 2.0f * p2;
        if (lane == k0 + 3) mykey = g_sq[b * NN + j3i] - 2.0f * p3;
    }

    // ---- select 8 smallest (winners' mykey consumed -> sentinel) ----
#pragma unroll
    for (int t = 0; t < KNN; ++t) {
        float v = mykey;
#pragma unroll
        for (int o = 16; o > 0; o >>= 1) v = fminf(v, __shfl_xor_sync(0xffffffffu, v, o));
        unsigned m = __ballot_sync(0xffffffffu, mykey == v);
        int src = __ffs(m) - 1;
        if (lane == src) mykey = 3.0e38f;
    }

    // ---- subtract the NCAND-KNN loser rows from the accumulated sum ----
    {
        unsigned lmask = __ballot_sync(0xffffffffu,
                                       (lane < NCAND) && (mykey < 1.0e38f));
#pragma unroll
        for (int t = 0; t < NCAND - KNN; ++t) {
            int src = __ffs(lmask) - 1;
            lmask &= lmask - 1;
            int jl = __shfl_sync(0xffffffffu, myidx, src);
            const float* p = Nb + (size_t)jl * CC + lane * 8;
            float4 y0 = *(const float4*)p;
            float4 y1 = *(const float4*)(p + 4);
            acc[0] -= y0.x; acc[1] -= y0.y; acc[2] -= y0.z; acc[3] -= y0.w;
            acc[4] -= y1.x; acc[5] -= y1.y; acc[6] -= y1.z; acc[7] -= y1.w;
        }
    }

    // ---- add 4-neighborhood grid rows ----
    int cnt = KNN;
    if (w > 0)      { const float* p = Nb + (size_t)(n - 1)  * CC + lane * 8;
        float4 y0 = *(const float4*)p; float4 y1 = *(const float4*)(p + 4);
        acc[0]+=y0.x; acc[1]+=y0.y; acc[2]+=y0.z; acc[3]+=y0.w;
        acc[4]+=y1.x; acc[5]+=y1.y; acc[6]+=y1.z; acc[7]+=y1.w; cnt++; }
    if (w < WW - 1) { const float* p = Nb + (size_t)(n + 1)  * CC + lane * 8;
        float4 y0 = *(const float4*)p; float4 y1 = *(const float4*)(p + 4);
        acc[0]+=y0.x; acc[1]+=y0.y; acc[2]+=y0.z; acc[3]+=y0.w;
        acc[4]+=y1.x; acc[5]+=y1.y; acc[6]+=y1.z; acc[7]+=y1.w; cnt++; }
    if (h > 0)      { const float* p = Nb + (size_t)(n - WW) * CC + lane * 8;
        float4 y0 = *(const float4*)p; float4 y1 = *(const float4*)(p + 4);
        acc[0]+=y0.x; acc[1]+=y0.y; acc[2]+=y0.z; acc[3]+=y0.w;
        acc[4]+=y1.x; acc[5]+=y1.y; acc[6]+=y1.z; acc[7]+=y1.w; cnt++; }
    if (h < HH - 1) { const float* p = Nb + (size_t)(n + WW) * CC + lane * 8;
        float4 y0 = *(const float4*)p; float4 y1 = *(const float4*)(p + 4);
        acc[0]+=y0.x; acc[1]+=y0.y; acc[2]+=y0.z; acc[3]+=y0.w;
        acc[4]+=y1.x; acc[5]+=y1.y; acc[6]+=y1.z; acc[7]+=y1.w; cnt++; }

    const float inv = 1.0f / (float)cnt;
    float xv[8] = {x0.x, x0.y, x0.z, x0.w, x1.x, x1.y, x1.z, x1.w};
    float y[8];
#pragma unroll
    for (int r2 = 0; r2 < 8; ++r2) y[r2] = acc[r2] * inv + xv[r2];

    // ---- LayerNorm over channels ----
    float s = 0.f;
#pragma unroll
    for (int r2 = 0; r2 < 8; ++r2) s += y[r2];
#pragma unroll
    for (int o = 16; o > 0; o >>= 1) s += __shfl_xor_sync(0xffffffffu, s, o);
    const float mu = s * (1.0f / CC);
    float v = 0.f;
#pragma unroll
    for (int r2 = 0; r2 < 8; ++r2) { float d = y[r2] - mu; v += d * d; }
#pragma unroll
    for (int o = 16; o > 0; o >>= 1) v += __shfl_xor_sync(0xffffffffu, v, o);
    const float rs = rsqrtf(v * (1.0f / CC) + 1e-5f);

    __shared__ float st[8][CC];
#pragma unroll
    for (int r2 = 0; r2 < 8; ++r2) {
        int c = lane * 8 + r2;
        st[wid][c] = (y[r2] - mu) * rs * gamma[c] + beta[c];
    }
    __syncthreads();

    const int c = threadIdx.x;
    float4 v0 = make_float4(st[0][c], st[1][c], st[2][c], st[3][c]);
    float4 v1 = make_float4(st[4][c], st[5][c], st[6][c], st[7][c]);
    size_t o = (size_t)b * CC * NN + (size_t)c * NN + n0;
    *(float4*)&out[o]     = v0;
    *(float4*)&out[o + 4] = v1;
}

// ---------------------------------------------------------------------------
extern "C" void kernel_launch(void* const* d_in, const int* in_sizes, int n_in,
                              void* d_out, int out_size) {
    const float* F     = (const float*)d_in[0];
    const float* gamma = (const float*)d_in[1];
    const float* beta  = (const float*)d_in[2];
    float* out = (float*)d_out;
    (void)in_sizes; (void)n_in; (void)out_size;

    k_transpose<<<dim3(NN / 32, CC / 32, BQ), dim3(32, 8)>>>(F);
    k_sq<<<dim3(NN / 8, BQ), 256>>>();

    cudaFuncSetAttribute(k_gram_sym,
                         cudaFuncAttributeMaxDynamicSharedMemorySize, SMB_TOT);
    k_gram_sym<<<dim3(NPAIR, BQ), 256, SMB_TOT>>>();

    k_refine<<<dim3(NN / 8, BQ), 256>>>(gamma, beta, out);
}

// round 15
// speedup vs baseline: 1.0144x; 1.0144x over previous
#include <cuda_runtime.h>
#include <cuda_fp16.h>
#include <cstdint>

// Problem constants (fixed shapes)
#define BQ  16
#define CC  256
#define HH  48
#define WW  48
#define NN  (HH*WW)      // 2304
#define KNN 8
#define KB  12           // per-tile candidate list length (sorted, best-first)
#define NSLOT 18         // one list per tile stripe
#define NLIST (NSLOT*KB) // 216 packed candidates per node
#define NCAND 12         // merged candidates that get exact rescore
#define TILE 128
#define NTILES (NN/TILE) // 18
#define NPAIR  171       // NTILES*(NTILES+1)/2
#define NOFFD  153       // off-diagonal pairs (scheduled first; diag last)

// gram smem layout (bytes); fp16 chunk row = 64 fp16 (128B) + 16 pad = 144
#define CRW    144
#define SMB_A0 0                   // also reused as merge buffer after MMA
#define SMB_A1 18432
#define SMB_B0 36864
#define SMB_B1 55296
#define SMB_SC 73728               // half2[128][65] = 33280
#define SCH2   65
#define SMB_SQI 107008             // half[128] (256 B)
#define SMB_SQJ 107264             // half[128] (256 B)
#define SMB_TOT 107520

#define PK_INIT 0xFC00FFFFu        // packed +inf key | idx 0xFFFF

// Scratch (device globals; no allocation allowed)
__device__ __align__(256) float    g_nodesT[BQ * NN * CC];  // fp32 features [B][N][C]
__device__ __align__(256) __half   g_half[BQ * NN * CC];    // fp16 copy for filter GEMM
__device__ __align__(256) float    g_sq[BQ * NN];           // squared norms
__device__ __align__(256) uint32_t g_ps[(size_t)BQ * NN * NLIST]; // packed cand lists

__device__ __forceinline__ uint32_t smem_u32(const void* p) {
    uint32_t a;
    asm("{ .reg .u64 t; cvta.to.shared.u64 t, %1; cvt.u32.u64 %0, t; }"
        : "=r"(a) : "l"(p));
    return a;
}
#define CP_ASYNC16(dst, src) \
    asm volatile("cp.async.cg.shared.global [%0], [%1], 16;" :: "r"(dst), "l"(src))
#define CP_COMMIT() asm volatile("cp.async.commit_group;" ::: "memory")
#define CP_WAIT(n)  asm volatile("cp.async.wait_group %0;" :: "n"(n) : "memory")

#define LDSM_X4(r0, r1, r2, r3, addr) \
    asm volatile("ldmatrix.sync.aligned.m8n8.x4.shared.b16 {%0,%1,%2,%3}, [%4];" \
        : "=r"(r0), "=r"(r1), "=r"(r2), "=r"(r3) : "r"(addr))

#define HMMA16(acc0, acc1, a0, a1, a2, a3, b0, b1) \
    asm volatile("mma.sync.aligned.m16n8k16.row.col.f16.f16.f16.f16 " \
        "{%0,%1}, {%2,%3,%4,%5}, {%6,%7}, {%0,%1};" \
        : "+r"(acc0), "+r"(acc1) \
        : "r"(a0), "r"(a1), "r"(a2), "r"(a3), "r"(b0), "r"(b1))

// half -> monotone u16 (asc uint == asc value)
__device__ __forceinline__ uint32_t h2mono(__half x) {
    unsigned short h = __half_as_ushort(x);
    unsigned short m = (unsigned short)(h ^ ((h & 0x8000) ? 0xFFFFu : 0x8000u));
    return (uint32_t)m;
}
// monotone u16 (hi half of packed) -> half
__device__ __forceinline__ __half mono2h(uint32_t p) {
    unsigned short m = (unsigned short)(p >> 16);
    unsigned short h = (unsigned short)(m ^ ((m & 0x8000) ? 0x8000u : 0xFFFFu));
    return __ushort_as_half(h);
}

// packed insert into uint32 top-KB list ([0] = worst/largest)
#define PINS(lst, p) do { \
    if ((p) < (lst)[0]) { \
        (lst)[0] = (p); \
        _Pragma("unroll") \
        for (int _t = 0; _t < KB - 1; ++_t) { \
            uint32_t _lo = min((lst)[_t], (lst)[_t + 1]); \
            uint32_t _hi = max((lst)[_t], (lst)[_t + 1]); \
            (lst)[_t] = _hi; (lst)[_t + 1] = _lo; \
        } \
    } \
} while (0)

// ---------------------------------------------------------------------------
// Kernel 1: transpose F[b][c][n] -> nodesT[b][n][c] (fp32 + fp16 copies)
// ---------------------------------------------------------------------------
__global__ void k_transpose(const float* __restrict__ F) {
    __shared__ float t[32][33];
    int b  = blockIdx.z;
    int n0 = blockIdx.x * 32;
    int c0 = blockIdx.y * 32;
    const float* Fb = F + (size_t)b * CC * NN;
    int tx = threadIdx.x, ty = threadIdx.y;  // 32 x 8
#pragma unroll
    for (int i = 0; i < 32; i += 8)
        t[ty + i][tx] = Fb[(size_t)(c0 + ty + i) * NN + n0 + tx];
    __syncthreads();
    float* out = g_nodesT + (size_t)b * NN * CC;
    __half* outh = g_half + (size_t)b * NN * CC;
#pragma unroll
    for (int i = 0; i < 32; i += 8) {
        float v = t[tx][ty + i];
        size_t o = (size_t)(n0 + ty + i) * CC + c0 + tx;
        out[o]  = v;
        outh[o] = __float2half(v);
    }
}

// ---------------------------------------------------------------------------
// Kernel 2: squared norms from g_nodesT (coalesced; warp per node)
// ---------------------------------------------------------------------------
__global__ void k_sq() {
    const int wid  = threadIdx.x >> 5;
    const int lane = threadIdx.x & 31;
    const int n = blockIdx.x * 8 + wid;
    const int b = blockIdx.y;
    const float* p = g_nodesT + (size_t)(b * NN + n) * CC + lane * 8;
    float4 a = *(const float4*)p;
    float4 c = *(const float4*)(p + 4);
    float s = a.x*a.x + a.y*a.y + a.z*a.z + a.w*a.w
            + c.x*c.x + c.y*c.y + c.z*c.z + c.w*c.w;
#pragma unroll
    for (int o = 16; o > 0; o >>= 1) s += __shfl_xor_sync(0xffffffffu, s, o);
    if (lane == 0) g_sq[b * NN + n] = s;
}

// ---------------------------------------------------------------------------
// Kernel 3: symmetric fp16 Gram — one CTA per tile-pair.
// Pair order: 153 off-diagonal pairs first, 18 diagonal pairs (cheapest —
// no col scan) last, so the partial tail wave runs the shortest CTAs.
// ---------------------------------------------------------------------------
__global__ __launch_bounds__(256, 2) void k_gram_sym() {
    extern __shared__ unsigned char smraw[];
    const uint32_t smb = smem_u32(smraw);
    uint32_t* Scw  = (uint32_t*)(smraw + SMB_SC);  // half2[128][65]
    __half*   sqih = (__half*)(smraw + SMB_SQI);   // [128]
    __half*   sqjh = (__half*)(smraw + SMB_SQJ);   // [128]
    uint32_t (*mbuf)[KB] = (uint32_t (*)[KB])(smraw + SMB_A0);  // overlay

    const int b = blockIdx.y;
    // pair mapping: [0,153) -> off-diag (it<jt); [153,171) -> diag (last waves)
    int it, jt;
    {
        int p = blockIdx.x;
        if (p >= NOFFD) { it = p - NOFFD; jt = it; }
        else {
            it = 0;
            while (p >= NTILES - 1 - it) { p -= NTILES - 1 - it; ++it; }
            jt = it + 1 + p;
        }
    }
    const int i0 = it * TILE, j0 = jt * TILE;

    const int tid = threadIdx.x;
    const int wid  = tid >> 5;
    const int lane = tid & 31;
    const int wm = wid >> 1;
    const int wn = wid & 1;
    const int grp = lane >> 2;
    const int tig = lane & 3;
    const int quad = lane >> 3;
    const int wi   = lane & 7;
    const __half* Hb = g_half + (size_t)b * NN * CC;

    const int crow  = tid >> 1;
    const int chalf = tid & 1;

    uint32_t aoff[2], boff[4];
#pragma unroll
    for (int mt = 0; mt < 2; ++mt) {
        int row = wm * 32 + mt * 16 + wi + 8 * (quad & 1);
        aoff[mt] = row * CRW + (quad >> 1) * 16;
    }
#pragma unroll
    for (int p = 0; p < 4; ++p) {
        int row = wn * 64 + p * 16 + wi + 8 * (quad >> 1);
        boff[p] = row * CRW + (quad & 1) * 16;
    }

    auto issue = [&](int q) {
        const int c = q, buf = q & 1;
        const char* asrc =
            (const char*)(Hb + (size_t)(i0 + crow) * CC + c * 64 + chalf * 32);
        const char* bsrc =
            (const char*)(Hb + (size_t)(j0 + crow) * CC + c * 64 + chalf * 32);
        uint32_t adst = smb + (buf ? SMB_A1 : SMB_A0) + crow * CRW + chalf * 64;
        uint32_t bdst = smb + (buf ? SMB_B1 : SMB_B0) + crow * CRW + chalf * 64;
#pragma unroll
        for (int i = 0; i < 4; ++i) {
            CP_ASYNC16(adst + i * 16, asrc + i * 16);
            CP_ASYNC16(bdst + i * 16, bsrc + i * 16);
        }
        CP_COMMIT();
    };

    issue(0);

    uint32_t acc[2][8][2];
#pragma unroll
    for (int mt = 0; mt < 2; ++mt)
#pragma unroll
        for (int nt = 0; nt < 8; ++nt)
            acc[mt][nt][0] = acc[mt][nt][1] = 0u;

    for (int q = 0; q < 4; ++q) {
        if (q + 1 < 4) { issue(q + 1); CP_WAIT(1); }
        else           {               CP_WAIT(0); }
        __syncthreads();

        if (q == 0 && tid < TILE) {
            sqih[tid] = __float2half(g_sq[b * NN + i0 + tid]);
            sqjh[tid] = __float2half(g_sq[b * NN + j0 + tid]);
        }

        const uint32_t abase = smb + ((q & 1) ? SMB_A1 : SMB_A0);
        const uint32_t bbase = smb + ((q & 1) ? SMB_B1 : SMB_B0);
#pragma unroll
        for (int ks = 0; ks < 4; ++ks) {
            const int ko = ks * 32;
            uint32_t a[2][4];
#pragma unroll
            for (int mt = 0; mt < 2; ++mt)
                LDSM_X4(a[mt][0], a[mt][1], a[mt][2], a[mt][3],
                        abase + aoff[mt] + ko);
            uint32_t bb[4][4];
#pragma unroll
            for (int p = 0; p < 4; ++p)
                LDSM_X4(bb[p][0], bb[p][1], bb[p][2], bb[p][3],
                        bbase + boff[p] + ko);
#pragma unroll
            for (int mt = 0; mt < 2; ++mt)
#pragma unroll
                for (int p = 0; p < 4; ++p) {
                    HMMA16(acc[mt][2*p][0],   acc[mt][2*p][1],
                           a[mt][0], a[mt][1], a[mt][2], a[mt][3],
                           bb[p][0], bb[p][1]);
                    HMMA16(acc[mt][2*p+1][0], acc[mt][2*p+1][1],
                           a[mt][0], a[mt][1], a[mt][2], a[mt][3],
                           bb[p][2], bb[p][3]);
                }
        }
        if (q < 3) __syncthreads();  // protect buffer q&1 before issue(q+2);
                                     // last chunk needs no trailing sync
    }

#pragma unroll
    for (int mt = 0; mt < 2; ++mt) {
        const int r0 = wm * 32 + mt * 16 + grp;
        const int cp = wn * 32 + tig;
#pragma unroll
        for (int nt = 0; nt < 8; ++nt) {
            Scw[r0 * SCH2 + cp + nt * 4]       = acc[mt][nt][0];
            Scw[(r0 + 8) * SCH2 + cp + nt * 4] = acc[mt][nt][1];
        }
    }
    __syncthreads();

    const bool diag = (it == jt);
    if (diag) {
        if (tid < TILE)
            ((__half*)Scw)[tid * (SCH2 * 2) + tid] = __ushort_as_half(0xFC00);
        __syncthreads();
    }

    uint32_t lst[KB];

    // ---- row-side scan ----
    {
        const int srow  = tid >> 1;
        const int shalf = tid & 1;
        const int ig    = i0 + srow;
#pragma unroll
        for (int k = 0; k < KB; ++k) lst[k] = PK_INIT;
        const __half2* srcrow = (const __half2*)Scw + srow * SCH2 + shalf * 32;
        const __half2* sq2    = (const __half2*)sqjh + shalf * 32;
        const int jbase = j0 + shalf * 64;
        const __half2 mtwo2 = __float2half2_rn(-2.0f);
        __half2 th2 = __half2half2(mono2h(lst[0]));
#pragma unroll 4
        for (int s = 0; s < 32; ++s) {
            __half2 key2 = __hfma2(srcrow[s], mtwo2, sq2[s]);
            if (!__hbge2(key2, th2)) {
                const int je = jbase + 2 * s;
                uint32_t p0 = (h2mono(__low2half(key2))  << 16) | (uint32_t)je;
                uint32_t p1 = (h2mono(__high2half(key2)) << 16) | (uint32_t)(je + 1);
                PINS(lst, p0);
                PINS(lst, p1);
                th2 = __half2half2(mono2h(lst[0]));
            }
        }
#pragma unroll
        for (int k = 0; k < KB; ++k) mbuf[tid][k] = lst[k];
        __syncwarp();
        if (shalf == 0) {
            int ia = KB - 1, ib = KB - 1;
            size_t base = ((size_t)(b * NN + ig) * NSLOT + jt) * KB;
#pragma unroll
            for (int t = 0; t < KB; ++t) {
                uint32_t va = mbuf[tid][ia], vb = mbuf[tid + 1][ib];
                if (va < vb) { g_ps[base + t] = va; --ia; }
                else         { g_ps[base + t] = vb; --ib; }
            }
        }
        __syncwarp();
    }

    // ---- col-side scan ----
    if (!diag) {
        const int c  = tid >> 1;
        const int hh = tid & 1;
#pragma unroll
        for (int k = 0; k < KB; ++k) lst[k] = PK_INIT;
        const __half* Sch = (const __half*)Scw;
        const __half mtwo = __float2half(-2.0f);
        __half th = mono2h(lst[0]);
#pragma unroll 4
        for (int r = 0; r < 64; ++r) {
            const int row = hh * 64 + r;
            __half d = Sch[row * (SCH2 * 2) + c];
            __half key = __hfma(d, mtwo, sqih[row]);
            if (__hlt(key, th)) {
                uint32_t p = (h2mono(key) << 16) | (uint32_t)(i0 + row);
                PINS(lst, p);
                th = mono2h(lst[0]);
            }
        }
#pragma unroll
        for (int k = 0; k < KB; ++k) mbuf[tid][k] = lst[k];
        __syncwarp();
        if (hh == 0) {
            int ia = KB - 1, ib = KB - 1;
            size_t base = ((size_t)(b * NN + j0 + c) * NSLOT + it) * KB;
#pragma unroll
            for (int t = 0; t < KB; ++t) {
                uint32_t va = mbuf[tid][ia], vb = mbuf[tid + 1][ib];
                if (va < vb) { g_ps[base + t] = va; --ia; }
                else         { g_ps[base + t] = vb; --ib; }
            }
        }
    }
}

// ---------------------------------------------------------------------------
// Kernel 4: tournament-merge 18 sorted lists -> top-12 by filter score,
// exact fp32 rescore -> top-8, aggregation + residual + LayerNorm.
// (R13 version — 44 regs, occupancy-friendly.)
// ---------------------------------------------------------------------------
__global__ __launch_bounds__(256) void k_refine(const float* __restrict__ gamma,
                                                const float* __restrict__ beta,
                                                float* __restrict__ out) {
    const int b    = blockIdx.y;
    const int wid  = threadIdx.x >> 5;
    const int lane = threadIdx.x & 31;
    const int n0   = blockIdx.x * 8;
    const int n    = n0 + wid;
    const int h = n / WW, w = n % WW;
    const float* Nb = g_nodesT + (size_t)b * NN * CC;

    const float* xi = Nb + (size_t)n * CC + lane * 8;
    float4 x0 = *(const float4*)xi;
    float4 x1 = *(const float4*)(xi + 4);

    // ---- load this node's 216 packed candidates (coalesced via smem) ----
    __shared__ uint32_t stage[8][224];
    {
        size_t base = (size_t)(b * NN + n) * NLIST;
#pragma unroll
        for (int k = 0; k < 7; ++k) {
            int e = lane + k * 32;
            stage[wid][e] = (e < NLIST) ? g_ps[base + e] : 0xFFFFFFFFu;
        }
    }
    __syncwarp();

    // ---- tournament: lane l < NSLOT owns sorted list l (best-first) ----
    uint32_t head = 0xFFFFFFFFu;
    int hp = 0;
    if (lane < NSLOT) head = stage[wid][lane * KB];
    uint32_t cword = 0xFFFFFFFFu;
#pragma unroll
    for (int t = 0; t < NCAND; ++t) {
        uint32_t wmv = __reduce_min_sync(0xffffffffu, head);
        if (lane == t) cword = wmv;
        unsigned msk = __ballot_sync(0xffffffffu, head == wmv);
        if (lane == (__ffs(msk) - 1)) {
            ++hp;
            head = (hp < KB) ? stage[wid][lane * KB + hp] : 0xFFFFFFFFu;
        }
    }
    int cand = (int)(cword & 0xFFFFu);

    // ---- exact rescore of NCAND candidates, 4 at a time ----
    float mykey = 3.0e38f;
    int   myidx = cand;
#pragma unroll
    for (int k0 = 0; k0 < NCAND; k0 += 4) {
        int j0i = __shfl_sync(0xffffffffu, cand, k0);
        int j1i = __shfl_sync(0xffffffffu, cand, k0 + 1);
        int j2i = __shfl_sync(0xffffffffu, cand, k0 + 2);
        int j3i = __shfl_sync(0xffffffffu, cand, k0 + 3);
        const float* r0p = Nb + (size_t)j0i * CC + lane * 8;
        const float* r1p = Nb + (size_t)j1i * CC + lane * 8;
        const float* r2p = Nb + (size_t)j2i * CC + lane * 8;
        const float* r3p = Nb + (size_t)j3i * CC + lane * 8;
        float4 a0 = *(const float4*)r0p, a1 = *(const float4*)(r0p + 4);
        float4 b0 = *(const float4*)r1p, b1 = *(const float4*)(r1p + 4);
        float4 c0 = *(const float4*)r2p, c1 = *(const float4*)(r2p + 4);
        float4 d0 = *(const float4*)r3p, d1 = *(const float4*)(r3p + 4);
        float p0 = x0.x*a0.x + x0.y*a0.y + x0.z*a0.z + x0.w*a0.w
                 + x1.x*a1.x + x1.y*a1.y + x1.z*a1.z + x1.w*a1.w;
        float p1 = x0.x*b0.x + x0.y*b0.y + x0.z*b0.z + x0.w*b0.w
                 + x1.x*b1.x + x1.y*b1.y + x1.z*b1.z + x1.w*b1.w;
        float p2 = x0.x*c0.x + x0.y*c0.y + x0.z*c0.z + x0.w*c0.w
                 + x1.x*c1.x + x1.y*c1.y + x1.z*c1.z + x1.w*c1.w;
        float p3 = x0.x*d0.x + x0.y*d0.y + x0.z*d0.z + x0.w*d0.w
                 + x1.x*d1.x + x1.y*d1.y + x1.z*d1.z + x1.w*d1.w;
#pragma unroll
        for (int o = 16; o > 0; o >>= 1) {
            p0 += __shfl_xor_sync(0xffffffffu, p0, o);
            p1 += __shfl_xor_sync(0xffffffffu, p1, o);
            p2 += __shfl_xor_sync(0xffffffffu, p2, o);
            p3 += __shfl_xor_sync(0xffffffffu, p3, o);
        }
        if (lane == k0)     mykey = g_sq[b * NN + j0i] - 2.0f * p0;
        if (lane == k0 + 1) mykey = g_sq[b * NN + j1i] - 2.0f * p1;
        if (lane == k0 + 2) mykey = g_sq[b * NN + j2i] - 2.0f * p2;
        if (lane == k0 + 3) mykey = g_sq[b * NN + j3i] - 2.0f * p3;
    }

    // ---- select 8 smallest; indices broadcast to all lanes ----
    int knn_j[KNN];
#pragma unroll
    for (int t = 0; t < KNN; ++t) {
        float v = mykey;
#pragma unroll
        for (int o = 16; o > 0; o >>= 1) v = fminf(v, __shfl_xor_sync(0xffffffffu, v, o));
        unsigned m = __ballot_sync(0xffffffffu, mykey == v);
        int src = __ffs(m) - 1;
        knn_j[t] = __shfl_sync(0xffffffffu, myidx, src);
        if (lane == src) mykey = 3.0e38f;
    }

    // ---- aggregate: 4-neighborhood grid + 8 knn, mean; residual ----
    float acc[8];
#pragma unroll
    for (int r2 = 0; r2 < 8; ++r2) acc[r2] = 0.f;
    int cnt = KNN;
#pragma unroll
    for (int t = 0; t < KNN; ++t) {
        const float* p = Nb + (size_t)knn_j[t] * CC + lane * 8;
        float4 y0 = *(const float4*)p;
        float4 y1 = *(const float4*)(p + 4);
        acc[0] += y0.x; acc[1] += y0.y; acc[2] += y0.z; acc[3] += y0.w;
        acc[4] += y1.x; acc[5] += y1.y; acc[6] += y1.z; acc[7] += y1.w;
    }
    if (w > 0)      { const float* p = Nb + (size_t)(n - 1)  * CC + lane * 8;
        float4 y0 = *(const float4*)p; float4 y1 = *(const float4*)(p + 4);
        acc[0]+=y0.x; acc[1]+=y0.y; acc[2]+=y0.z; acc[3]+=y0.w;
        acc[4]+=y1.x; acc[5]+=y1.y; acc[6]+=y1.z; acc[7]+=y1.w; cnt++; }
    if (w < WW - 1) { const float* p = Nb + (size_t)(n + 1)  * CC + lane * 8;
        float4 y0 = *(const float4*)p; float4 y1 = *(const float4*)(p + 4);
        acc[0]+=y0.x; acc[1]+=y0.y; acc[2]+=y0.z; acc[3]+=y0.w;
        acc[4]+=y1.x; acc[5]+=y1.y; acc[6]+=y1.z; acc[7]+=y1.w; cnt++; }
    if (h > 0)      { const float* p = Nb + (size_t)(n - WW) * CC + lane * 8;
        float4 y0 = *(const float4*)p; float4 y1 = *(const float4*)(p + 4);
        acc[0]+=y0.x; acc[1]+=y0.y; acc[2]+=y0.z; acc[3]+=y0.w;
        acc[4]+=y1.x; acc[5]+=y1.y; acc[6]+=y1.z; acc[7]+=y1.w; cnt++; }
    if (h < HH - 1) { const float* p = Nb + (size_t)(n + WW) * CC + lane * 8;
        float4 y0 = *(const float4*)p; float4 y1 = *(const float4*)(p + 4);
        acc[0]+=y0.x; acc[1]+=y0.y; acc[2]+=y0.z; acc[3]+=y0.w;
        acc[4]+=y1.x; acc[5]+=y1.y; acc[6]+=y1.z; acc[7]+=y1.w; cnt++; }

    const float inv = 1.0f / (float)cnt;
    float xv[8] = {x0.x, x0.y, x0.z, x0.w, x1.x, x1.y, x1.z, x1.w};
    float y[8];
#pragma unroll
    for (int r2 = 0; r2 < 8; ++r2) y[r2] = acc[r2] * inv + xv[r2];

    // ---- LayerNorm over channels ----
    float s = 0.f;
#pragma unroll
    for (int r2 = 0; r2 < 8; ++r2) s += y[r2];
#pragma unroll
    for (int o = 16; o > 0; o >>= 1) s += __shfl_xor_sync(0xffffffffu, s, o);
    const float mu = s * (1.0f / CC);
    float v = 0.f;
#pragma unroll
    for (int r2 = 0; r2 < 8; ++r2) { float d = y[r2] - mu; v += d * d; }
#pragma unroll
    for (int o = 16; o > 0; o >>= 1) v += __shfl_xor_sync(0xffffffffu, v, o);
    const float rs = rsqrtf(v * (1.0f / CC) + 1e-5f);

    __shared__ float st[8][CC];
#pragma unroll
    for (int r2 = 0; r2 < 8; ++r2) {
        int c = lane * 8 + r2;
        st[wid][c] = (y[r2] - mu) * rs * gamma[c] + beta[c];
    }
    __syncthreads();

    const int c = threadIdx.x;
    float4 v0 = make_float4(st[0][c], st[1][c], st[2][c], st[3][c]);
    float4 v1 = make_float4(st[4][c], st[5][c], st[6][c], st[7][c]);
    size_t o = (size_t)b * CC * NN + (size_t)c * NN + n0;
    *(float4*)&out[o]     = v0;
    *(float4*)&out[o + 4] = v1;
}

// ---------------------------------------------------------------------------
extern "C" void kernel_launch(void* const* d_in, const int* in_sizes, int n_in,
                              void* d_out, int out_size) {
    const float* F     = (const float*)d_in[0];
    const float* gamma = (const float*)d_in[1];
    const float* beta  = (const float*)d_in[2];
    float* out = (float*)d_out;
    (void)in_sizes; (void)n_in; (void)out_size;

    k_transpose<<<dim3(NN / 32, CC / 32, BQ), dim3(32, 8)>>>(F);
    k_sq<<<dim3(NN / 8, BQ), 256>>>();

    cudaFuncSetAttribute(k_gram_sym,
                         cudaFuncAttributeMaxDynamicSharedMemorySize, SMB_TOT);
    k_gram_sym<<<dim3(NPAIR, BQ), 256, SMB_TOT>>>();

    k_refine<<<dim3(NN / 8, BQ), 256>>>(gamma, beta, out);
}

// round 16
// speedup vs baseline: 1.0303x; 1.0157x over previous
#include <cuda_runtime.h>
#include <cuda_fp16.h>
#include <cstdint>

// Problem constants (fixed shapes)
#define BQ  16
#define CC  256
#define HH  48
#define WW  48
#define NN  (HH*WW)      // 2304
#define KNN 8
#define KB  12           // per-tile candidate list length (sorted, best-first)
#define NSLOT 18         // one list per tile stripe
#define NLIST (NSLOT*KB) // 216 packed candidates per node
#define NCAND 12         // merged candidates that get exact rescore
#define TILE 128
#define NTILES (NN/TILE) // 18
#define NPAIR  171       // NTILES*(NTILES+1)/2
#define NOFFD  153       // off-diagonal pairs (scheduled first; diag last)

// gram smem layout (bytes); fp16 chunk row = 64 fp16 (128B) + 16 pad = 144
#define CRW    144
#define SMB_A0 0                   // also reused as merge buffer after MMA
#define SMB_A1 18432
#define SMB_B0 36864
#define SMB_B1 55296
#define SMB_SC 73728               // half2[128][65] = 33280
#define SCH2   65
#define SMB_SQI 107008             // half[128] (256 B)
#define SMB_SQJ 107264             // half[128] (256 B)
#define SMB_TOT 107520

#define PK_INIT 0xFC00FFFFu        // packed +inf key | idx 0xFFFF

// Scratch (device globals; no allocation allowed)
__device__ __align__(256) float    g_nodesT[BQ * NN * CC];  // fp32 features [B][N][C]
__device__ __align__(256) __half   g_half[BQ * NN * CC];    // fp16 copy for filter GEMM
__device__ __align__(256) float    g_sq[BQ * NN];           // squared norms
__device__ __align__(256) uint32_t g_ps[(size_t)BQ * NN * NLIST]; // packed cand lists

__device__ __forceinline__ uint32_t smem_u32(const void* p) {
    uint32_t a;
    asm("{ .reg .u64 t; cvta.to.shared.u64 t, %1; cvt.u32.u64 %0, t; }"
        : "=r"(a) : "l"(p));
    return a;
}
#define CP_ASYNC16(dst, src) \
    asm volatile("cp.async.cg.shared.global [%0], [%1], 16;" :: "r"(dst), "l"(src))
#define CP_COMMIT() asm volatile("cp.async.commit_group;" ::: "memory")
#define CP_WAIT(n)  asm volatile("cp.async.wait_group %0;" :: "n"(n) : "memory")

#define LDSM_X4(r0, r1, r2, r3, addr) \
    asm volatile("ldmatrix.sync.aligned.m8n8.x4.shared.b16 {%0,%1,%2,%3}, [%4];" \
        : "=r"(r0), "=r"(r1), "=r"(r2), "=r"(r3) : "r"(addr))

#define HMMA16(acc0, acc1, a0, a1, a2, a3, b0, b1) \
    asm volatile("mma.sync.aligned.m16n8k16.row.col.f16.f16.f16.f16 " \
        "{%0,%1}, {%2,%3,%4,%5}, {%6,%7}, {%0,%1};" \
        : "+r"(acc0), "+r"(acc1) \
        : "r"(a0), "r"(a1), "r"(a2), "r"(a3), "r"(b0), "r"(b1))

// half -> monotone u16 (asc uint == asc value)
__device__ __forceinline__ uint32_t h2mono(__half x) {
    unsigned short h = __half_as_ushort(x);
    unsigned short m = (unsigned short)(h ^ ((h & 0x8000) ? 0xFFFFu : 0x8000u));
    return (uint32_t)m;
}
// monotone u16 (hi half of packed) -> half
__device__ __forceinline__ __half mono2h(uint32_t p) {
    unsigned short m = (unsigned short)(p >> 16);
    unsigned short h = (unsigned short)(m ^ ((m & 0x8000) ? 0x8000u : 0xFFFFu));
    return __ushort_as_half(h);
}

// packed insert into uint32 top-KB list ([0] = worst/largest)
#define PINS(lst, p) do { \
    if ((p) < (lst)[0]) { \
        (lst)[0] = (p); \
        _Pragma("unroll") \
        for (int _t = 0; _t < KB - 1; ++_t) { \
            uint32_t _lo = min((lst)[_t], (lst)[_t + 1]); \
            uint32_t _hi = max((lst)[_t], (lst)[_t + 1]); \
            (lst)[_t] = _hi; (lst)[_t + 1] = _lo; \
        } \
    } \
} while (0)

// ---------------------------------------------------------------------------
// Kernel 0: zero g_sq (transpose accumulates into it atomically)
// ---------------------------------------------------------------------------
__global__ void k_zero() {
    int i = blockIdx.x * blockDim.x + threadIdx.x;
    if (i < BQ * NN) g_sq[i] = 0.f;
}

// ---------------------------------------------------------------------------
// Kernel 1: transpose F[b][c][n] -> nodesT[b][n][c] (fp32 + fp16 copies),
// fused squared-norm partials (warp-reduce 32 channels, atomicAdd).
// ---------------------------------------------------------------------------
__global__ void k_transpose(const float* __restrict__ F) {
    __shared__ float t[32][33];
    int b  = blockIdx.z;
    int n0 = blockIdx.x * 32;
    int c0 = blockIdx.y * 32;
    const float* Fb = F + (size_t)b * CC * NN;
    int tx = threadIdx.x, ty = threadIdx.y;  // 32 x 8 (warp = fixed ty)
#pragma unroll
    for (int i = 0; i < 32; i += 8)
        t[ty + i][tx] = Fb[(size_t)(c0 + ty + i) * NN + n0 + tx];
    __syncthreads();
    float* out = g_nodesT + (size_t)b * NN * CC;
    __half* outh = g_half + (size_t)b * NN * CC;
#pragma unroll
    for (int i = 0; i < 32; i += 8) {
        float v = t[tx][ty + i];
        size_t o = (size_t)(n0 + ty + i) * CC + c0 + tx;
        out[o]  = v;
        outh[o] = __float2half(v);
        float s = v * v;
#pragma unroll
        for (int off = 16; off > 0; off >>= 1)
            s += __shfl_xor_sync(0xffffffffu, s, off);
        if (tx == 0) atomicAdd(&g_sq[b * NN + n0 + ty + i], s);
    }
}

// ---------------------------------------------------------------------------
// Kernel 3: symmetric fp16 Gram — one CTA per tile-pair.
// Pair order: 153 off-diagonal pairs first, 18 diagonal pairs (cheapest —
// no col scan) last. Single-sync chunk loop: the top barrier both publishes
// chunk q and guards buffer (q&1) reuse by issue(q+1).
// ---------------------------------------------------------------------------
__global__ __launch_bounds__(256, 2) void k_gram_sym() {
    extern __shared__ unsigned char smraw[];
    const uint32_t smb = smem_u32(smraw);
    uint32_t* Scw  = (uint32_t*)(smraw + SMB_SC);  // half2[128][65]
    __half*   sqih = (__half*)(smraw + SMB_SQI);   // [128]
    __half*   sqjh = (__half*)(smraw + SMB_SQJ);   // [128]
    uint32_t (*mbuf)[KB] = (uint32_t (*)[KB])(smraw + SMB_A0);  // overlay

    const int b = blockIdx.y;
    // pair mapping: [0,153) -> off-diag (it<jt); [153,171) -> diag (last waves)
    int it, jt;
    {
        int p = blockIdx.x;
        if (p >= NOFFD) { it = p - NOFFD; jt = it; }
        else {
            it = 0;
            while (p >= NTILES - 1 - it) { p -= NTILES - 1 - it; ++it; }
            jt = it + 1 + p;
        }
    }
    const int i0 = it * TILE, j0 = jt * TILE;

    const int tid = threadIdx.x;
    const int wid  = tid >> 5;
    const int lane = tid & 31;
    const int wm = wid >> 1;
    const int wn = wid & 1;
    const int grp = lane >> 2;
    const int tig = lane & 3;
    const int quad = lane >> 3;
    const int wi   = lane & 7;
    const __half* Hb = g_half + (size_t)b * NN * CC;

    const int crow  = tid >> 1;
    const int chalf = tid & 1;

    uint32_t aoff[2], boff[4];
#pragma unroll
    for (int mt = 0; mt < 2; ++mt) {
        int row = wm * 32 + mt * 16 + wi + 8 * (quad & 1);
        aoff[mt] = row * CRW + (quad >> 1) * 16;
    }
#pragma unroll
    for (int p = 0; p < 4; ++p) {
        int row = wn * 64 + p * 16 + wi + 8 * (quad >> 1);
        boff[p] = row * CRW + (quad & 1) * 16;
    }

    auto issue = [&](int q) {
        const int c = q, buf = q & 1;
        const char* asrc =
            (const char*)(Hb + (size_t)(i0 + crow) * CC + c * 64 + chalf * 32);
        const char* bsrc =
            (const char*)(Hb + (size_t)(j0 + crow) * CC + c * 64 + chalf * 32);
        uint32_t adst = smb + (buf ? SMB_A1 : SMB_A0) + crow * CRW + chalf * 64;
        uint32_t bdst = smb + (buf ? SMB_B1 : SMB_B0) + crow * CRW + chalf * 64;
#pragma unroll
        for (int i = 0; i < 4; ++i) {
            CP_ASYNC16(adst + i * 16, asrc + i * 16);
            CP_ASYNC16(bdst + i * 16, bsrc + i * 16);
        }
        CP_COMMIT();
    };

    issue(0);

    uint32_t acc[2][8][2];
#pragma unroll
    for (int mt = 0; mt < 2; ++mt)
#pragma unroll
        for (int nt = 0; nt < 8; ++nt)
            acc[mt][nt][0] = acc[mt][nt][1] = 0u;

    for (int q = 0; q < 4; ++q) {
        CP_WAIT(0);          // chunk q landed
        __syncthreads();     // publishes chunk q; all warps done with buf q&1's
                             // previous contents -> safe to overwrite below
        if (q == 0 && tid < TILE) {
            sqih[tid] = __float2half(g_sq[b * NN + i0 + tid]);
            sqjh[tid] = __float2half(g_sq[b * NN + j0 + tid]);
        }
        if (q + 1 < 4) issue(q + 1);   // overlaps MMA of chunk q

        const uint32_t abase = smb + ((q & 1) ? SMB_A1 : SMB_A0);
        const uint32_t bbase = smb + ((q & 1) ? SMB_B1 : SMB_B0);
#pragma unroll
        for (int ks = 0; ks < 4; ++ks) {
            const int ko = ks * 32;
            uint32_t a[2][4];
#pragma unroll
            for (int mt = 0; mt < 2; ++mt)
                LDSM_X4(a[mt][0], a[mt][1], a[mt][2], a[mt][3],
                        abase + aoff[mt] + ko);
            uint32_t bb[4][4];
#pragma unroll
            for (int p = 0; p < 4; ++p)
                LDSM_X4(bb[p][0], bb[p][1], bb[p][2], bb[p][3],
                        bbase + boff[p] + ko);
#pragma unroll
            for (int mt = 0; mt < 2; ++mt)
#pragma unroll
                for (int p = 0; p < 4; ++p) {
                    HMMA16(acc[mt][2*p][0],   acc[mt][2*p][1],
                           a[mt][0], a[mt][1], a[mt][2], a[mt][3],
                           bb[p][0], bb[p][1]);
                    HMMA16(acc[mt][2*p+1][0], acc[mt][2*p+1][1],
                           a[mt][0], a[mt][1], a[mt][2], a[mt][3],
                           bb[p][2], bb[p][3]);
                }
        }
    }

#pragma unroll
    for (int mt = 0; mt < 2; ++mt) {
        const int r0 = wm * 32 + mt * 16 + grp;
        const int cp = wn * 32 + tig;
#pragma unroll
        for (int nt = 0; nt < 8; ++nt) {
            Scw[r0 * SCH2 + cp + nt * 4]       = acc[mt][nt][0];
            Scw[(r0 + 8) * SCH2 + cp + nt * 4] = acc[mt][nt][1];
        }
    }
    __syncthreads();

    const bool diag = (it == jt);
    if (diag) {
        if (tid < TILE)
            ((__half*)Scw)[tid * (SCH2 * 2) + tid] = __ushort_as_half(0xFC00);
        __syncthreads();
    }

    uint32_t lst[KB];

    // ---- row-side scan ----
    {
        const int srow  = tid >> 1;
        const int shalf = tid & 1;
        const int ig    = i0 + srow;
#pragma unroll
        for (int k = 0; k < KB; ++k) lst[k] = PK_INIT;
        const __half2* srcrow = (const __half2*)Scw + srow * SCH2 + shalf * 32;
        const __half2* sq2    = (const __half2*)sqjh + shalf * 32;
        const int jbase = j0 + shalf * 64;
        const __half2 mtwo2 = __float2half2_rn(-2.0f);
        __half2 th2 = __half2half2(mono2h(lst[0]));
#pragma unroll 4
        for (int s = 0; s < 32; ++s) {
            __half2 key2 = __hfma2(srcrow[s], mtwo2, sq2[s]);
            if (!__hbge2(key2, th2)) {
                const int je = jbase + 2 * s;
                uint32_t p0 = (h2mono(__low2half(key2))  << 16) | (uint32_t)je;
                uint32_t p1 = (h2mono(__high2half(key2)) << 16) | (uint32_t)(je + 1);
                PINS(lst, p0);
                PINS(lst, p1);
                th2 = __half2half2(mono2h(lst[0]));
            }
        }
#pragma unroll
        for (int k = 0; k < KB; ++k) mbuf[tid][k] = lst[k];
        __syncwarp();
        if (shalf == 0) {
            int ia = KB - 1, ib = KB - 1;
            size_t base = ((size_t)(b * NN + ig) * NSLOT + jt) * KB;
#pragma unroll
            for (int t = 0; t < KB; ++t) {
                uint32_t va = mbuf[tid][ia], vb = mbuf[tid + 1][ib];
                if (va < vb) { g_ps[base + t] = va; --ia; }
                else         { g_ps[base + t] = vb; --ib; }
            }
        }
        __syncwarp();
    }

    // ---- col-side scan ----
    if (!diag) {
        const int c  = tid >> 1;
        const int hh = tid & 1;
#pragma unroll
        for (int k = 0; k < KB; ++k) lst[k] = PK_INIT;
        const __half* Sch = (const __half*)Scw;
        const __half mtwo = __float2half(-2.0f);
        __half th = mono2h(lst[0]);
#pragma unroll 4
        for (int r = 0; r < 64; ++r) {
            const int row = hh * 64 + r;
            __half d = Sch[row * (SCH2 * 2) + c];
            __half key = __hfma(d, mtwo, sqih[row]);
            if (__hlt(key, th)) {
                uint32_t p = (h2mono(key) << 16) | (uint32_t)(i0 + row);
                PINS(lst, p);
                th = mono2h(lst[0]);
            }
        }
#pragma unroll
        for (int k = 0; k < KB; ++k) mbuf[tid][k] = lst[k];
        __syncwarp();
        if (hh == 0) {
            int ia = KB - 1, ib = KB - 1;
            size_t base = ((size_t)(b * NN + j0 + c) * NSLOT + it) * KB;
#pragma unroll
            for (int t = 0; t < KB; ++t) {
                uint32_t va = mbuf[tid][ia], vb = mbuf[tid + 1][ib];
                if (va < vb) { g_ps[base + t] = va; --ia; }
                else         { g_ps[base + t] = vb; --ib; }
            }
        }
    }
}

// ---------------------------------------------------------------------------
// Kernel 4: tournament-merge 18 sorted lists -> top-12 by filter score,
// exact fp32 rescore -> top-8, aggregation + residual + LayerNorm.
// ---------------------------------------------------------------------------
__global__ __launch_bounds__(256) void k_refine(const float* __restrict__ gamma,
                                                const float* __restrict__ beta,
                                                float* __restrict__ out) {
    const int b    = blockIdx.y;
    const int wid  = threadIdx.x >> 5;
    const int lane = threadIdx.x & 31;
    const int n0   = blockIdx.x * 8;
    const int n    = n0 + wid;
    const int h = n / WW, w = n % WW;
    const float* Nb = g_nodesT + (size_t)b * NN * CC;

    const float* xi = Nb + (size_t)n * CC + lane * 8;
    float4 x0 = *(const float4*)xi;
    float4 x1 = *(const float4*)(xi + 4);

    // ---- load this node's 216 packed candidates (coalesced via smem) ----
    __shared__ uint32_t stage[8][224];
    {
        size_t base = (size_t)(b * NN + n) * NLIST;
#pragma unroll
        for (int k = 0; k < 7; ++k) {
            int e = lane + k * 32;
            stage[wid][e] = (e < NLIST) ? g_ps[base + e] : 0xFFFFFFFFu;
        }
    }
    __syncwarp();

    // ---- tournament: lane l < NSLOT owns sorted list l (best-first) ----
    uint32_t head = 0xFFFFFFFFu;
    int hp = 0;
    if (lane < NSLOT) head = stage[wid][lane * KB];
    uint32_t cword = 0xFFFFFFFFu;
#pragma unroll
    for (int t = 0; t < NCAND; ++t) {
        uint32_t wmv = __reduce_min_sync(0xffffffffu, head);
        if (lane == t) cword = wmv;
        unsigned msk = __ballot_sync(0xffffffffu, head == wmv);
        if (lane == (__ffs(msk) - 1)) {
            ++hp;
            head = (hp < KB) ? stage[wid][lane * KB + hp] : 0xFFFFFFFFu;
        }
    }
    int cand = (int)(cword & 0xFFFFu);

    // ---- exact rescore of NCAND candidates, 4 at a time ----
    float mykey = 3.0e38f;
    int   myidx = cand;
#pragma unroll
    for (int k0 = 0; k0 < NCAND; k0 += 4) {
        int j0i = __shfl_sync(0xffffffffu, cand, k0);
        int j1i = __shfl_sync(0xffffffffu, cand, k0 + 1);
        int j2i = __shfl_sync(0xffffffffu, cand, k0 + 2);
        int j3i = __shfl_sync(0xffffffffu, cand, k0 + 3);
        const float* r0p = Nb + (size_t)j0i * CC + lane * 8;
        const float* r1p = Nb + (size_t)j1i * CC + lane * 8;
        const float* r2p = Nb + (size_t)j2i * CC + lane * 8;
        const float* r3p = Nb + (size_t)j3i * CC + lane * 8;
        float4 a0 = *(const float4*)r0p, a1 = *(const float4*)(r0p + 4);
        float4 b0 = *(const float4*)r1p, b1 = *(const float4*)(r1p + 4);
        float4 c0 = *(const float4*)r2p, c1 = *(const float4*)(r2p + 4);
        float4 d0 = *(const float4*)r3p, d1 = *(const float4*)(r3p + 4);
        float p0 = x0.x*a0.x + x0.y*a0.y + x0.z*a0.z + x0.w*a0.w
                 + x1.x*a1.x + x1.y*a1.y + x1.z*a1.z + x1.w*a1.w;
        float p1 = x0.x*b0.x + x0.y*b0.y + x0.z*b0.z + x0.w*b0.w
                 + x1.x*b1.x + x1.y*b1.y + x1.z*b1.z + x1.w*b1.w;
        float p2 = x0.x*c0.x + x0.y*c0.y + x0.z*c0.z + x0.w*c0.w
                 + x1.x*c1.x + x1.y*c1.y + x1.z*c1.z + x1.w*c1.w;
        float p3 = x0.x*d0.x + x0.y*d0.y + x0.z*d0.z + x0.w*d0.w
                 + x1.x*d1.x + x1.y*d1.y + x1.z*d1.z + x1.w*d1.w;
#pragma unroll
        for (int o = 16; o > 0; o >>= 1) {
            p0 += __shfl_xor_sync(0xffffffffu, p0, o);
            p1 += __shfl_xor_sync(0xffffffffu, p1, o);
            p2 += __shfl_xor_sync(0xffffffffu, p2, o);
            p3 += __shfl_xor_sync(0xffffffffu, p3, o);
        }
        if (lane == k0)     mykey = g_sq[b * NN + j0i] - 2.0f * p0;
        if (lane == k0 + 1) mykey = g_sq[b * NN + j1i] - 2.0f * p1;
        if (lane == k0 + 2) mykey = g_sq[b * NN + j2i] - 2.0f * p2;
        if (lane == k0 + 3) mykey = g_sq[b * NN + j3i] - 2.0f * p3;
    }

    // ---- select 8 smallest; indices broadcast to all lanes ----
    int knn_j[KNN];
#pragma unroll
    for (int t = 0; t < KNN; ++t) {
        float v = mykey;
#pragma unroll
        for (int o = 16; o > 0; o >>= 1) v = fminf(v, __shfl_xor_sync(0xffffffffu, v, o));
        unsigned m = __ballot_sync(0xffffffffu, mykey == v);
        int src = __ffs(m) - 1;
        knn_j[t] = __shfl_sync(0xffffffffu, myidx, src);
        if (lane == src) mykey = 3.0e38f;
    }

    // ---- aggregate: 4-neighborhood grid + 8 knn, mean; residual ----
    float acc[8];
#pragma unroll
    for (int r2 = 0; r2 < 8; ++r2) acc[r2] = 0.f;
    int cnt = KNN;
#pragma unroll
    for (int t = 0; t < KNN; ++t) {
        const float* p = Nb + (size_t)knn_j[t] * CC + lane * 8;
        float4 y0 = *(const float4*)p;
        float4 y1 = *(const float4*)(p + 4);
        acc[0] += y0.x; acc[1] += y0.y; acc[2] += y0.z; acc[3] += y0.w;
        acc[4] += y1.x; acc[5] += y1.y; acc[6] += y1.z; acc[7] += y1.w;
    }
    if (w > 0)      { const float* p = Nb + (size_t)(n - 1)  * CC + lane * 8;
        float4 y0 = *(const float4*)p; float4 y1 = *(const float4*)(p + 4);
        acc[0]+=y0.x; acc[1]+=y0.y; acc[2]+=y0.z; acc[3]+=y0.w;
        acc[4]+=y1.x; acc[5]+=y1.y; acc[6]+=y1.z; acc[7]+=y1.w; cnt++; }
    if (w < WW - 1) { const float* p = Nb + (size_t)(n + 1)  * CC + lane * 8;
        float4 y0 = *(const float4*)p; float4 y1 = *(const float4*)(p + 4);
        acc[0]+=y0.x; acc[1]+=y0.y; acc[2]+=y0.z; acc[3]+=y0.w;
        acc[4]+=y1.x; acc[5]+=y1.y; acc[6]+=y1.z; acc[7]+=y1.w; cnt++; }
    if (h > 0)      { const float* p = Nb + (size_t)(n - WW) * CC + lane * 8;
        float4 y0 = *(const float4*)p; float4 y1 = *(const float4*)(p + 4);
        acc[0]+=y0.x; acc[1]+=y0.y; acc[2]+=y0.z; acc[3]+=y0.w;
        acc[4]+=y1.x; acc[5]+=y1.y; acc[6]+=y1.z; acc[7]+=y1.w; cnt++; }
    if (h < HH - 1) { const float* p = Nb + (size_t)(n + WW) * CC + lane * 8;
        float4 y0 = *(const float4*)p; float4 y1 = *(const float4*)(p + 4);
        acc[0]+=y0.x; acc[1]+=y0.y; acc[2]+=y0.z; acc[3]+=y0.w;
        acc[4]+=y1.x; acc[5]+=y1.y; acc[6]+=y1.z; acc[7]+=y1.w; cnt++; }

    const float inv = 1.0f / (float)cnt;
    float xv[8] = {x0.x, x0.y, x0.z, x0.w, x1.x, x1.y, x1.z, x1.w};
    float y[8];
#pragma unroll
    for (int r2 = 0; r2 < 8; ++r2) y[r2] = acc[r2] * inv + xv[r2];

    // ---- LayerNorm over channels ----
    float s = 0.f;
#pragma unroll
    for (int r2 = 0; r2 < 8; ++r2) s += y[r2];
#pragma unroll
    for (int o = 16; o > 0; o >>= 1) s += __shfl_xor_sync(0xffffffffu, s, o);
    const float mu = s * (1.0f / CC);
    float v = 0.f;
#pragma unroll
    for (int r2 = 0; r2 < 8; ++r2) { float d = y[r2] - mu; v += d * d; }
#pragma unroll
    for (int o = 16; o > 0; o >>= 1) v += __shfl_xor_sync(0xffffffffu, v, o);
    const float rs = rsqrtf(v * (1.0f / CC) + 1e-5f);

    __shared__ float st[8][CC];
#pragma unroll
    for (int r2 = 0; r2 < 8; ++r2) {
        int c = lane * 8 + r2;
        st[wid][c] = (y[r2] - mu) * rs * gamma[c] + beta[c];
    }
    __syncthreads();

    const int c = threadIdx.x;
    float4 v0 = make_float4(st[0][c], st[1][c], st[2][c], st[3][c]);
    float4 v1 = make_float4(st[4][c], st[5][c], st[6][c], st[7][c]);
    size_t o = (size_t)b * CC * NN + (size_t)c * NN + n0;
    *(float4*)&out[o]     = v0;
    *(float4*)&out[o + 4] = v1;
}

// ---------------------------------------------------------------------------
extern "C" void kernel_launch(void* const* d_in, const int* in_sizes, int n_in,
                              void* d_out, int out_size) {
    const float* F     = (const float*)d_in[0];
    const float* gamma = (const float*)d_in[1];
    const float* beta  = (const float*)d_in[2];
    float* out = (float*)d_out;
    (void)in_sizes; (void)n_in; (void)out_size;

    k_zero<<<(BQ * NN + 255) / 256, 256>>>();
    k_transpose<<<dim3(NN / 32, CC / 32, BQ), dim3(32, 8)>>>(F);

    cudaFuncSetAttribute(k_gram_sym,
                         cudaFuncAttributeMaxDynamicSharedMemorySize, SMB_TOT);
    k_gram_sym<<<dim3(NPAIR, BQ), 256, SMB_TOT>>>();

    k_refine<<<dim3(NN / 8, BQ), 256>>>(gamma, beta, out);
}

// round 17
// speedup vs baseline: 1.0311x; 1.0008x over previous
#include <cuda_runtime.h>
#include <cuda_fp16.h>
#include <cstdint>

// Problem constants (fixed shapes)
#define BQ  16
#define CC  256
#define HH  48
#define WW  48
#define NN  (HH*WW)      // 2304
#define KNN 8
#define KB  12           // per-tile candidate list length (sorted, best-first)
#define NSLOT 18         // one list per tile stripe
#define NLIST (NSLOT*KB) // 216 packed candidates per node
#define NCAND 12         // merged candidates that get exact rescore
#define TILE 128
#define NTILES (NN/TILE) // 18
#define NPAIR  171       // NTILES*(NTILES+1)/2
#define NOFFD  153       // off-diagonal pairs (scheduled first; diag last)

// gram smem layout (bytes); fp16 chunk row = 64 fp16 (128B) + 16 pad = 144
#define CRW    144
#define SMB_A0 0                   // also reused as merge buffer after MMA
#define SMB_A1 18432
#define SMB_B0 36864
#define SMB_B1 55296
#define SMB_SC 73728               // half2[128][65] = 33280
#define SCH2   65
#define SMB_SQI 107008             // half[128] (256 B)
#define SMB_SQJ 107264             // half[128] (256 B)
#define SMB_TOT 107520

#define PK_INIT 0xFC00FFFFu        // packed +inf key | idx 0xFFFF

// Scratch (device globals; no allocation allowed)
__device__ __align__(256) float    g_nodesT[BQ * NN * CC];  // fp32 features [B][N][C]
__device__ __align__(256) __half   g_half[BQ * NN * CC];    // fp16 copy for filter GEMM
__device__ __align__(256) float    g_sq[BQ * NN];           // squared norms
__device__ __align__(256) uint32_t g_ps[(size_t)BQ * NN * NLIST]; // packed cand lists

__device__ __forceinline__ uint32_t smem_u32(const void* p) {
    uint32_t a;
    asm("{ .reg .u64 t; cvta.to.shared.u64 t, %1; cvt.u32.u64 %0, t; }"
        : "=r"(a) : "l"(p));
    return a;
}
#define CP_ASYNC16(dst, src) \
    asm volatile("cp.async.cg.shared.global [%0], [%1], 16;" :: "r"(dst), "l"(src))
#define CP_COMMIT() asm volatile("cp.async.commit_group;" ::: "memory")
#define CP_WAIT(n)  asm volatile("cp.async.wait_group %0;" :: "n"(n) : "memory")

#define LDSM_X4(r0, r1, r2, r3, addr) \
    asm volatile("ldmatrix.sync.aligned.m8n8.x4.shared.b16 {%0,%1,%2,%3}, [%4];" \
        : "=r"(r0), "=r"(r1), "=r"(r2), "=r"(r3) : "r"(addr))

#define HMMA16(acc0, acc1, a0, a1, a2, a3, b0, b1) \
    asm volatile("mma.sync.aligned.m16n8k16.row.col.f16.f16.f16.f16 " \
        "{%0,%1}, {%2,%3,%4,%5}, {%6,%7}, {%0,%1};" \
        : "+r"(acc0), "+r"(acc1) \
        : "r"(a0), "r"(a1), "r"(a2), "r"(a3), "r"(b0), "r"(b1))

// half -> monotone u16 (asc uint == asc value)
__device__ __forceinline__ uint32_t h2mono(__half x) {
    unsigned short h = __half_as_ushort(x);
    unsigned short m = (unsigned short)(h ^ ((h & 0x8000) ? 0xFFFFu : 0x8000u));
    return (uint32_t)m;
}
// monotone u16 (hi half of packed) -> half
__device__ __forceinline__ __half mono2h(uint32_t p) {
    unsigned short m = (unsigned short)(p >> 16);
    unsigned short h = (unsigned short)(m ^ ((m & 0x8000) ? 0x8000u : 0xFFFFu));
    return __ushort_as_half(h);
}

// packed insert into uint32 top-KB list ([0] = worst/largest)
#define PINS(lst, p) do { \
    if ((p) < (lst)[0]) { \
        (lst)[0] = (p); \
        _Pragma("unroll") \
        for (int _t = 0; _t < KB - 1; ++_t) { \
            uint32_t _lo = min((lst)[_t], (lst)[_t + 1]); \
            uint32_t _hi = max((lst)[_t], (lst)[_t + 1]); \
            (lst)[_t] = _hi; (lst)[_t + 1] = _lo; \
        } \
    } \
} while (0)

// ---------------------------------------------------------------------------
// Kernel 0: zero g_sq (transpose accumulates into it atomically)
// ---------------------------------------------------------------------------
__global__ void k_zero() {
    int i = blockIdx.x * blockDim.x + threadIdx.x;
    if (i < BQ * NN) g_sq[i] = 0.f;
}

// ---------------------------------------------------------------------------
// Kernel 1: transpose F[b][c][n] -> nodesT[b][n][c] (fp32 + fp16 copies),
// fused squared-norm partials (warp-reduce 32 channels, atomicAdd).
// ---------------------------------------------------------------------------
__global__ void k_transpose(const float* __restrict__ F) {
    __shared__ float t[32][33];
    int b  = blockIdx.z;
    int n0 = blockIdx.x * 32;
    int c0 = blockIdx.y * 32;
    const float* Fb = F + (size_t)b * CC * NN;
    int tx = threadIdx.x, ty = threadIdx.y;  // 32 x 8 (warp = fixed ty)
#pragma unroll
    for (int i = 0; i < 32; i += 8)
        t[ty + i][tx] = Fb[(size_t)(c0 + ty + i) * NN + n0 + tx];
    __syncthreads();
    float* out = g_nodesT + (size_t)b * NN * CC;
    __half* outh = g_half + (size_t)b * NN * CC;
#pragma unroll
    for (int i = 0; i < 32; i += 8) {
        float v = t[tx][ty + i];
        size_t o = (size_t)(n0 + ty + i) * CC + c0 + tx;
        out[o]  = v;
        outh[o] = __float2half(v);
        float s = v * v;
#pragma unroll
        for (int off = 16; off > 0; off >>= 1)
            s += __shfl_xor_sync(0xffffffffu, s, off);
        if (tx == 0) atomicAdd(&g_sq[b * NN + n0 + ty + i], s);
    }
}

// ---------------------------------------------------------------------------
// Kernel 3: symmetric fp16 Gram — one CTA per tile-pair.
// Pair order: 153 off-diagonal pairs first, 18 diagonal pairs (cheapest —
// no col scan) last. Single-sync chunk loop; sq vectors loaded in prologue.
// ---------------------------------------------------------------------------
__global__ __launch_bounds__(256, 2) void k_gram_sym() {
    extern __shared__ unsigned char smraw[];
    const uint32_t smb = smem_u32(smraw);
    uint32_t* Scw  = (uint32_t*)(smraw + SMB_SC);  // half2[128][65]
    __half*   sqih = (__half*)(smraw + SMB_SQI);   // [128]
    __half*   sqjh = (__half*)(smraw + SMB_SQJ);   // [128]
    uint32_t (*mbuf)[KB] = (uint32_t (*)[KB])(smraw + SMB_A0);  // overlay

    const int b = blockIdx.y;
    // pair mapping: [0,153) -> off-diag (it<jt); [153,171) -> diag (last waves)
    int it, jt;
    {
        int p = blockIdx.x;
        if (p >= NOFFD) { it = p - NOFFD; jt = it; }
        else {
            it = 0;
            while (p >= NTILES - 1 - it) { p -= NTILES - 1 - it; ++it; }
            jt = it + 1 + p;
        }
    }
    const int i0 = it * TILE, j0 = jt * TILE;

    const int tid = threadIdx.x;
    const int wid  = tid >> 5;
    const int lane = tid & 31;
    const int wm = wid >> 1;
    const int wn = wid & 1;
    const int grp = lane >> 2;
    const int tig = lane & 3;
    const int quad = lane >> 3;
    const int wi   = lane & 7;
    const __half* Hb = g_half + (size_t)b * NN * CC;

    const int crow  = tid >> 1;
    const int chalf = tid & 1;

    uint32_t aoff[2], boff[4];
#pragma unroll
    for (int mt = 0; mt < 2; ++mt) {
        int row = wm * 32 + mt * 16 + wi + 8 * (quad & 1);
        aoff[mt] = row * CRW + (quad >> 1) * 16;
    }
#pragma unroll
    for (int p = 0; p < 4; ++p) {
        int row = wn * 64 + p * 16 + wi + 8 * (quad >> 1);
        boff[p] = row * CRW + (quad & 1) * 16;
    }

    auto issue = [&](int q) {
        const int c = q, buf = q & 1;
        const char* asrc =
            (const char*)(Hb + (size_t)(i0 + crow) * CC + c * 64 + chalf * 32);
        const char* bsrc =
            (const char*)(Hb + (size_t)(j0 + crow) * CC + c * 64 + chalf * 32);
        uint32_t adst = smb + (buf ? SMB_A1 : SMB_A0) + crow * CRW + chalf * 64;
        uint32_t bdst = smb + (buf ? SMB_B1 : SMB_B0) + crow * CRW + chalf * 64;
#pragma unroll
        for (int i = 0; i < 4; ++i) {
            CP_ASYNC16(adst + i * 16, asrc + i * 16);
            CP_ASYNC16(bdst + i * 16, bsrc + i * 16);
        }
        CP_COMMIT();
    };

    // prologue: sq vectors (region disjoint from chunk buffers; ordered
    // before the scan by the post-MMA staging sync)
    if (tid < TILE) {
        sqih[tid] = __float2half(g_sq[b * NN + i0 + tid]);
        sqjh[tid] = __float2half(g_sq[b * NN + j0 + tid]);
    }
    issue(0);

    uint32_t acc[2][8][2];
#pragma unroll
    for (int mt = 0; mt < 2; ++mt)
#pragma unroll
        for (int nt = 0; nt < 8; ++nt)
            acc[mt][nt][0] = acc[mt][nt][1] = 0u;

    for (int q = 0; q < 4; ++q) {
        CP_WAIT(0);          // chunk q landed
        __syncthreads();     // publishes chunk q; guards buf (q&1) reuse
        if (q + 1 < 4) issue(q + 1);   // overlaps MMA of chunk q

        const uint32_t abase = smb + ((q & 1) ? SMB_A1 : SMB_A0);
        const uint32_t bbase = smb + ((q & 1) ? SMB_B1 : SMB_B0);
#pragma unroll
        for (int ks = 0; ks < 4; ++ks) {
            const int ko = ks * 32;
            uint32_t a[2][4];
#pragma unroll
            for (int mt = 0; mt < 2; ++mt)
                LDSM_X4(a[mt][0], a[mt][1], a[mt][2], a[mt][3],
                        abase + aoff[mt] + ko);
            uint32_t bb[4][4];
#pragma unroll
            for (int p = 0; p < 4; ++p)
                LDSM_X4(bb[p][0], bb[p][1], bb[p][2], bb[p][3],
                        bbase + boff[p] + ko);
#pragma unroll
            for (int mt = 0; mt < 2; ++mt)
#pragma unroll
                for (int p = 0; p < 4; ++p) {
                    HMMA16(acc[mt][2*p][0],   acc[mt][2*p][1],
                           a[mt][0], a[mt][1], a[mt][2], a[mt][3],
                           bb[p][0], bb[p][1]);
                    HMMA16(acc[mt][2*p+1][0], acc[mt][2*p+1][1],
                           a[mt][0], a[mt][1], a[mt][2], a[mt][3],
                           bb[p][2], bb[p][3]);
                }
        }
    }

#pragma unroll
    for (int mt = 0; mt < 2; ++mt) {
        const int r0 = wm * 32 + mt * 16 + grp;
        const int cp = wn * 32 + tig;
#pragma unroll
        for (int nt = 0; nt < 8; ++nt) {
            Scw[r0 * SCH2 + cp + nt * 4]       = acc[mt][nt][0];
            Scw[(r0 + 8) * SCH2 + cp + nt * 4] = acc[mt][nt][1];
        }
    }
    __syncthreads();

    const bool diag = (it == jt);
    if (diag) {
        if (tid < TILE)
            ((__half*)Scw)[tid * (SCH2 * 2) + tid] = __ushort_as_half(0xFC00);
        __syncthreads();
    }

    uint32_t lst[KB];

    // ---- row-side scan ----
    {
        const int srow  = tid >> 1;
        const int shalf = tid & 1;
        const int ig    = i0 + srow;
#pragma unroll
        for (int k = 0; k < KB; ++k) lst[k] = PK_INIT;
        const __half2* srcrow = (const __half2*)Scw + srow * SCH2 + shalf * 32;
        const __half2* sq2    = (const __half2*)sqjh + shalf * 32;
        const int jbase = j0 + shalf * 64;
        const __half2 mtwo2 = __float2half2_rn(-2.0f);
        __half2 th2 = __half2half2(mono2h(lst[0]));
#pragma unroll 4
        for (int s = 0; s < 32; ++s) {
            __half2 key2 = __hfma2(srcrow[s], mtwo2, sq2[s]);
            if (!__hbge2(key2, th2)) {
                const int je = jbase + 2 * s;
                uint32_t p0 = (h2mono(__low2half(key2))  << 16) | (uint32_t)je;
                uint32_t p1 = (h2mono(__high2half(key2)) << 16) | (uint32_t)(je + 1);
                PINS(lst, p0);
                PINS(lst, p1);
                th2 = __half2half2(mono2h(lst[0]));
            }
        }
#pragma unroll
        for (int k = 0; k < KB; ++k) mbuf[tid][k] = lst[k];
        __syncwarp();
        if (shalf == 0) {
            int ia = KB - 1, ib = KB - 1;
            size_t base = ((size_t)(b * NN + ig) * NSLOT + jt) * KB;
#pragma unroll
            for (int t = 0; t < KB; ++t) {
                uint32_t va = mbuf[tid][ia], vb = mbuf[tid + 1][ib];
                if (va < vb) { g_ps[base + t] = va; --ia; }
                else         { g_ps[base + t] = vb; --ib; }
            }
        }
        __syncwarp();
    }

    // ---- col-side scan ----
    if (!diag) {
        const int c  = tid >> 1;
        const int hh = tid & 1;
#pragma unroll
        for (int k = 0; k < KB; ++k) lst[k] = PK_INIT;
        const __half* Sch = (const __half*)Scw;
        const __half mtwo = __float2half(-2.0f);
        __half th = mono2h(lst[0]);
#pragma unroll 4
        for (int r = 0; r < 64; ++r) {
            const int row = hh * 64 + r;
            __half d = Sch[row * (SCH2 * 2) + c];
            __half key = __hfma(d, mtwo, sqih[row]);
            if (__hlt(key, th)) {
                uint32_t p = (h2mono(key) << 16) | (uint32_t)(i0 + row);
                PINS(lst, p);
                th = mono2h(lst[0]);
            }
        }
#pragma unroll
        for (int k = 0; k < KB; ++k) mbuf[tid][k] = lst[k];
        __syncwarp();
        if (hh == 0) {
            int ia = KB - 1, ib = KB - 1;
            size_t base = ((size_t)(b * NN + j0 + c) * NSLOT + it) * KB;
#pragma unroll
            for (int t = 0; t < KB; ++t) {
                uint32_t va = mbuf[tid][ia], vb = mbuf[tid + 1][ib];
                if (va < vb) { g_ps[base + t] = va; --ia; }
                else         { g_ps[base + t] = vb; --ib; }
            }
        }
    }
}

// ---------------------------------------------------------------------------
// Kernel 4: tournament-merge 18 sorted lists -> top-12 by filter score,
// exact fp32 rescore -> top-8, aggregation + residual + LayerNorm.
// 6 blocks/SM requested (75% occ) — refine is L1-latency-bound.
// ---------------------------------------------------------------------------
__global__ __launch_bounds__(256, 6) void k_refine(const float* __restrict__ gamma,
                                                   const float* __restrict__ beta,
                                                   float* __restrict__ out) {
    const int b    = blockIdx.y;
    const int wid  = threadIdx.x >> 5;
    const int lane = threadIdx.x & 31;
    const int n0   = blockIdx.x * 8;
    const int n    = n0 + wid;
    const int h = n / WW, w = n % WW;
    const float* Nb = g_nodesT + (size_t)b * NN * CC;

    const float* xi = Nb + (size_t)n * CC + lane * 8;
    float4 x0 = *(const float4*)xi;
    float4 x1 = *(const float4*)(xi + 4);

    // ---- load this node's 216 packed candidates (coalesced via smem) ----
    __shared__ uint32_t stage[8][224];
    {
        size_t base = (size_t)(b * NN + n) * NLIST;
#pragma unroll
        for (int k = 0; k < 7; ++k) {
            int e = lane + k * 32;
            stage[wid][e] = (e < NLIST) ? g_ps[base + e] : 0xFFFFFFFFu;
        }
    }
    __syncwarp();

    // ---- tournament: lane l < NSLOT owns sorted list l (best-first) ----
    uint32_t head = 0xFFFFFFFFu;
    int hp = 0;
    if (lane < NSLOT) head = stage[wid][lane * KB];
    uint32_t cword = 0xFFFFFFFFu;
#pragma unroll
    for (int t = 0; t < NCAND; ++t) {
        uint32_t wmv = __reduce_min_sync(0xffffffffu, head);
        if (lane == t) cword = wmv;
        unsigned msk = __ballot_sync(0xffffffffu, head == wmv);
        if (lane == (__ffs(msk) - 1)) {
            ++hp;
            head = (hp < KB) ? stage[wid][lane * KB + hp] : 0xFFFFFFFFu;
        }
    }
    int cand = (int)(cword & 0xFFFFu);

    // ---- exact rescore of NCAND candidates, 4 at a time ----
    float mykey = 3.0e38f;
    int   myidx = cand;
#pragma unroll
    for (int k0 = 0; k0 < NCAND; k0 += 4) {
        int j0i = __shfl_sync(0xffffffffu, cand, k0);
        int j1i = __shfl_sync(0xffffffffu, cand, k0 + 1);
        int j2i = __shfl_sync(0xffffffffu, cand, k0 + 2);
        int j3i = __shfl_sync(0xffffffffu, cand, k0 + 3);
        const float* r0p = Nb + (size_t)j0i * CC + lane * 8;
        const float* r1p = Nb + (size_t)j1i * CC + lane * 8;
        const float* r2p = Nb + (size_t)j2i * CC + lane * 8;
        const float* r3p = Nb + (size_t)j3i * CC + lane * 8;
        float4 a0 = *(const float4*)r0p, a1 = *(const float4*)(r0p + 4);
        float4 b0 = *(const float4*)r1p, b1 = *(const float4*)(r1p + 4);
        float4 c0 = *(const float4*)r2p, c1 = *(const float4*)(r2p + 4);
        float4 d0 = *(const float4*)r3p, d1 = *(const float4*)(r3p + 4);
        float p0 = x0.x*a0.x + x0.y*a0.y + x0.z*a0.z + x0.w*a0.w
                 + x1.x*a1.x + x1.y*a1.y + x1.z*a1.z + x1.w*a1.w;
        float p1 = x0.x*b0.x + x0.y*b0.y + x0.z*b0.z + x0.w*b0.w
                 + x1.x*b1.x + x1.y*b1.y + x1.z*b1.z + x1.w*b1.w;
        float p2 = x0.x*c0.x + x0.y*c0.y + x0.z*c0.z + x0.w*c0.w
                 + x1.x*c1.x + x1.y*c1.y + x1.z*c1.z + x1.w*c1.w;
        float p3 = x0.x*d0.x + x0.y*d0.y + x0.z*d0.z + x0.w*d0.w
                 + x1.x*d1.x + x1.y*d1.y + x1.z*d1.z + x1.w*d1.w;
#pragma unroll
        for (int o = 16; o > 0; o >>= 1) {
            p0 += __shfl_xor_sync(0xffffffffu, p0, o);
            p1 += __shfl_xor_sync(0xffffffffu, p1, o);
            p2 += __shfl_xor_sync(0xffffffffu, p2, o);
            p3 += __shfl_xor_sync(0xffffffffu, p3, o);
        }
        if (lane == k0)     mykey = g_sq[b * NN + j0i] - 2.0f * p0;
        if (lane == k0 + 1) mykey = g_sq[b * NN + j1i] - 2.0f * p1;
        if (lane == k0 + 2) mykey = g_sq[b * NN + j2i] - 2.0f * p2;
        if (lane == k0 + 3) mykey = g_sq[b * NN + j3i] - 2.0f * p3;
    }

    // ---- select 8 smallest; indices broadcast to all lanes ----
    int knn_j[KNN];
#pragma unroll
    for (int t = 0; t < KNN; ++t) {
        float v = mykey;
#pragma unroll
        for (int o = 16; o > 0; o >>= 1) v = fminf(v, __shfl_xor_sync(0xffffffffu, v, o));
        unsigned m = __ballot_sync(0xffffffffu, mykey == v);
        int src = __ffs(m) - 1;
        knn_j[t] = __shfl_sync(0xffffffffu, myidx, src);
        if (lane == src) mykey = 3.0e38f;
    }

    // ---- aggregate: 4-neighborhood grid + 8 knn, mean; residual ----
    float acc[8];
#pragma unroll
    for (int r2 = 0; r2 < 8; ++r2) acc[r2] = 0.f;
    int cnt = KNN;
#pragma unroll
    for (int t = 0; t < KNN; ++t) {
        const float* p = Nb + (size_t)knn_j[t] * CC + lane * 8;
        float4 y0 = *(const float4*)p;
        float4 y1 = *(const float4*)(p + 4);
        acc[0] += y0.x; acc[1] += y0.y; acc[2] += y0.z; acc[3] += y0.w;
        acc[4] += y1.x; acc[5] += y1.y; acc[6] += y1.z; acc[7] += y1.w;
    }
    if (w > 0)      { const float* p = Nb + (size_t)(n - 1)  * CC + lane * 8;
        float4 y0 = *(const float4*)p; float4 y1 = *(const float4*)(p + 4);
        acc[0]+=y0.x; acc[1]+=y0.y; acc[2]+=y0.z; acc[3]+=y0.w;
        acc[4]+=y1.x; acc[5]+=y1.y; acc[6]+=y1.z; acc[7]+=y1.w; cnt++; }
    if (w < WW - 1) { const float* p = Nb + (size_t)(n + 1)  * CC + lane * 8;
        float4 y0 = *(const float4*)p; float4 y1 = *(const float4*)(p + 4);
        acc[0]+=y0.x; acc[1]+=y0.y; acc[2]+=y0.z; acc[3]+=y0.w;
        acc[4]+=y1.x; acc[5]+=y1.y; acc[6]+=y1.z; acc[7]+=y1.w; cnt++; }
    if (h > 0)      { const float* p = Nb + (size_t)(n - WW) * CC + lane * 8;
        float4 y0 = *(const float4*)p; float4 y1 = *(const float4*)(p + 4);
        acc[0]+=y0.x; acc[1]+=y0.y; acc[2]+=y0.z; acc[3]+=y0.w;
        acc[4]+=y1.x; acc[5]+=y1.y; acc[6]+=y1.z; acc[7]+=y1.w; cnt++; }
    if (h < HH - 1) { const float* p = Nb + (size_t)(n + WW) * CC + lane * 8;
        float4 y0 = *(const float4*)p; float4 y1 = *(const float4*)(p + 4);
        acc[0]+=y0.x; acc[1]+=y0.y; acc[2]+=y0.z; acc[3]+=y0.w;
        acc[4]+=y1.x; acc[5]+=y1.y; acc[6]+=y1.z; acc[7]+=y1.w; cnt++; }

    const float inv = 1.0f / (float)cnt;
    float xv[8] = {x0.x, x0.y, x0.z, x0.w, x1.x, x1.y, x1.z, x1.w};
    float y[8];
#pragma unroll
    for (int r2 = 0; r2 < 8; ++r2) y[r2] = acc[r2] * inv + xv[r2];

    // ---- LayerNorm over channels ----
    float s = 0.f;
#pragma unroll
    for (int r2 = 0; r2 < 8; ++r2) s += y[r2];
#pragma unroll
    for (int o = 16; o > 0; o >>= 1) s += __shfl_xor_sync(0xffffffffu, s, o);
    const float mu = s * (1.0f / CC);
    float v = 0.f;
#pragma unroll
    for (int r2 = 0; r2 < 8; ++r2) { float d = y[r2] - mu; v += d * d; }
#pragma unroll
    for (int o = 16; o > 0; o >>= 1) v += __shfl_xor_sync(0xffffffffu, v, o);
    const float rs = rsqrtf(v * (1.0f / CC) + 1e-5f);

    __shared__ float st[8][CC];
#pragma unroll
    for (int r2 = 0; r2 < 8; ++r2) {
        int c = lane * 8 + r2;
        st[wid][c] = (y[r2] - mu) * rs * gamma[c] + beta[c];
    }
    __syncthreads();

    const int c = threadIdx.x;
    float4 v0 = make_float4(st[0][c], st[1][c], st[2][c], st[3][c]);
    float4 v1 = make_float4(st[4][c], st[5][c], st[6][c], st[7][c]);
    size_t o = (size_t)b * CC * NN + (size_t)c * NN + n0;
    *(float4*)&out[o]     = v0;
    *(float4*)&out[o + 4] = v1;
}

// ---------------------------------------------------------------------------
extern "C" void kernel_launch(void* const* d_in, const int* in_sizes, int n_in,
                              void* d_out, int out_size) {
    const float* F     = (const float*)d_in[0];
    const float* gamma = (const float*)d_in[1];
    const float* beta  = (const float*)d_in[2];
    float* out = (float*)d_out;
    (void)in_sizes; (void)n_in; (void)out_size;

    k_zero<<<(BQ * NN + 255) / 256, 256>>>();
    k_transpose<<<dim3(NN / 32, CC / 32, BQ), dim3(32, 8)>>>(F);

    cudaFuncSetAttribute(k_gram_sym,
                         cudaFuncAttributeMaxDynamicSharedMemorySize, SMB_TOT);
    k_gram_sym<<<dim3(NPAIR, BQ), 256, SMB_TOT>>>();

    k_refine<<<dim3(NN / 8, BQ), 256>>>(gamma, beta, out);
}